// round 1
// baseline (speedup 1.0000x reference)
#include <cuda_runtime.h>
#include <math.h>

#define D_MODEL 1024
#define SEQ     2048
#define BATCH   2
#define HEADS   16
#define HDIM    64
#define MROWS   (BATCH*SEQ)   // 4096
#define PAD     68            // smem row pitch for transposed 64-col tiles (keeps 16B align)

// Scratch (no allocations allowed) — 4 x 16MB
__device__ float g_q[(size_t)MROWS * D_MODEL];
__device__ float g_k[(size_t)MROWS * D_MODEL];
__device__ float g_v[(size_t)MROWS * D_MODEL];
__device__ float g_ctx[(size_t)MROWS * D_MODEL];

// ---------------------------------------------------------------------------
// C[M,N] = A[M,K] @ W[N,K]^T (+ bias[n]).  128x128 tile, KT=16, 256 threads,
// 8x8 per thread with split fragments (rows ty*4 / 64+ty*4, cols tx*4 / 64+tx*4)
// so all compute LDS are conflict-free float4.
// ---------------------------------------------------------------------------
__global__ __launch_bounds__(256) void gemm128(
    const float* __restrict__ A, const float* __restrict__ W,
    const float* __restrict__ bias, float* __restrict__ C,
    int M, int N, int K)
{
    __shared__ float As[16][128];
    __shared__ float Bs[16][128];
    const int tid = threadIdx.x;
    const int tx = tid & 15, ty = tid >> 4;
    const int m0 = blockIdx.y * 128, n0 = blockIdx.x * 128;

    float acc[8][8];
#pragma unroll
    for (int i = 0; i < 8; i++)
#pragma unroll
        for (int j = 0; j < 8; j++) acc[i][j] = 0.0f;

    const int lr = tid >> 1;        // 0..127 (tile row)
    const int lk = (tid & 1) * 8;   // 0 or 8 (k offset)
    const float* Ap = A + (size_t)(m0 + lr) * K + lk;
    const float* Wp = W + (size_t)(n0 + lr) * K + lk;

    for (int k0 = 0; k0 < K; k0 += 16) {
        float4 a0 = *(const float4*)(Ap + k0);
        float4 a1 = *(const float4*)(Ap + k0 + 4);
        float4 b0 = *(const float4*)(Wp + k0);
        float4 b1 = *(const float4*)(Wp + k0 + 4);
        __syncthreads();
        As[lk+0][lr]=a0.x; As[lk+1][lr]=a0.y; As[lk+2][lr]=a0.z; As[lk+3][lr]=a0.w;
        As[lk+4][lr]=a1.x; As[lk+5][lr]=a1.y; As[lk+6][lr]=a1.z; As[lk+7][lr]=a1.w;
        Bs[lk+0][lr]=b0.x; Bs[lk+1][lr]=b0.y; Bs[lk+2][lr]=b0.z; Bs[lk+3][lr]=b0.w;
        Bs[lk+4][lr]=b1.x; Bs[lk+5][lr]=b1.y; Bs[lk+6][lr]=b1.z; Bs[lk+7][lr]=b1.w;
        __syncthreads();
#pragma unroll
        for (int kk = 0; kk < 16; kk++) {
            float a[8], b[8];
            *(float4*)&a[0] = *(const float4*)&As[kk][ty*4];
            *(float4*)&a[4] = *(const float4*)&As[kk][64 + ty*4];
            *(float4*)&b[0] = *(const float4*)&Bs[kk][tx*4];
            *(float4*)&b[4] = *(const float4*)&Bs[kk][64 + tx*4];
#pragma unroll
            for (int i = 0; i < 8; i++)
#pragma unroll
                for (int j = 0; j < 8; j++)
                    acc[i][j] = fmaf(a[i], b[j], acc[i][j]);
        }
    }

#pragma unroll
    for (int i = 0; i < 8; i++) {
        int row = m0 + ((i < 4) ? (ty*4 + i) : (64 + ty*4 + (i-4)));
#pragma unroll
        for (int jg = 0; jg < 2; jg++) {
            int col = n0 + jg*64 + tx*4;
            float4 r;
            float b0v = bias ? bias[col+0] : 0.0f;
            float b1v = bias ? bias[col+1] : 0.0f;
            float b2v = bias ? bias[col+2] : 0.0f;
            float b3v = bias ? bias[col+3] : 0.0f;
            r.x = acc[i][jg*4+0] + b0v;
            r.y = acc[i][jg*4+1] + b1v;
            r.z = acc[i][jg*4+2] + b2v;
            r.w = acc[i][jg*4+3] + b3v;
            *(float4*)&C[(size_t)row * N + col] = r;
        }
    }
}

// ---------------------------------------------------------------------------
// Flash attention per (b,h): Q,K,V are contiguous [2048,64] row-major heads.
// 64-row q-tile per block, 256 threads (16x16), 4x4 fragments for both GEMMs.
// Logits scale = 1/64 (module divides by head_dim). Causal; fully-masked
// k-tiles skipped (kt <= qt). Output written to ctx[b, s, h*64+d].
// ---------------------------------------------------------------------------
__global__ __launch_bounds__(256) void attn64(
    const float* __restrict__ Qg, const float* __restrict__ Kg,
    const float* __restrict__ Vg, float* __restrict__ ctx)
{
    extern __shared__ float sm[];
    float* QsT = sm;                    // [64][PAD]  (d-major, transposed)
    float* KsT = QsT + 64*PAD;          // [64][PAD]
    float* PsT = KsT + 64*PAD;          // [64][PAD]  (k-major, transposed P)
    float* Vs  = PsT + 64*PAD;          // [64][64]   (natural)

    const int tid = threadIdx.x;
    const int tx = tid & 15, ty = tid >> 4;
    const int bh = blockIdx.y;          // b*16 + h == contiguous head slice index
    const int qt = blockIdx.x;
    const int qbase = qt * 64;
    const float* Qh = Qg + (size_t)bh * SEQ * HDIM;
    const float* Kh = Kg + (size_t)bh * SEQ * HDIM;
    const float* Vh = Vg + (size_t)bh * SEQ * HDIM;
    const float scale = 1.0f / 64.0f;

    // Load Q tile transposed + pre-scaled
#pragma unroll
    for (int u = 0; u < 4; u++) {
        int f = tid + 256*u;
        int r = f >> 4, c = (f & 15) << 2;
        float4 q4 = *(const float4*)(Qh + (size_t)(qbase + r)*HDIM + c);
        QsT[(c+0)*PAD + r] = q4.x * scale;
        QsT[(c+1)*PAD + r] = q4.y * scale;
        QsT[(c+2)*PAD + r] = q4.z * scale;
        QsT[(c+3)*PAD + r] = q4.w * scale;
    }

    float m_i[4], l_i[4], o[4][4];
#pragma unroll
    for (int i = 0; i < 4; i++) {
        m_i[i] = -1e30f; l_i[i] = 0.0f;
#pragma unroll
        for (int j = 0; j < 4; j++) o[i][j] = 0.0f;
    }

    for (int kt = 0; kt <= qt; kt++) {
        const int kbase = kt * 64;
        __syncthreads();   // prior iter's smem reads (and Q-tile write) complete
#pragma unroll
        for (int u = 0; u < 4; u++) {
            int f = tid + 256*u;
            int r = f >> 4, c = (f & 15) << 2;
            float4 k4 = *(const float4*)(Kh + (size_t)(kbase + r)*HDIM + c);
            KsT[(c+0)*PAD + r] = k4.x;
            KsT[(c+1)*PAD + r] = k4.y;
            KsT[(c+2)*PAD + r] = k4.z;
            KsT[(c+3)*PAD + r] = k4.w;
            float4 v4 = *(const float4*)(Vh + (size_t)(kbase + r)*HDIM + c);
            *(float4*)&Vs[r*64 + c] = v4;
        }
        __syncthreads();

        // S = (Q*scale) @ K^T
        float s[4][4];
#pragma unroll
        for (int i = 0; i < 4; i++)
#pragma unroll
            for (int j = 0; j < 4; j++) s[i][j] = 0.0f;
#pragma unroll 8
        for (int d = 0; d < 64; d++) {
            float4 a4 = *(const float4*)&QsT[d*PAD + ty*4];
            float4 b4 = *(const float4*)&KsT[d*PAD + tx*4];
            float a[4] = {a4.x, a4.y, a4.z, a4.w};
            float b[4] = {b4.x, b4.y, b4.z, b4.w};
#pragma unroll
            for (int i = 0; i < 4; i++)
#pragma unroll
                for (int j = 0; j < 4; j++)
                    s[i][j] = fmaf(a[i], b[j], s[i][j]);
        }

        // Causal mask (only the diagonal tile needs it; kbase == qbase there)
        if (kt == qt) {
#pragma unroll
            for (int i = 0; i < 4; i++)
#pragma unroll
                for (int j = 0; j < 4; j++)
                    if (tx*4 + j > ty*4 + i) s[i][j] = -1e30f;
        }

        // Online softmax (row stats across 16 lanes via xor-shuffle, width 16)
#pragma unroll
        for (int i = 0; i < 4; i++) {
            float rm = fmaxf(fmaxf(s[i][0], s[i][1]), fmaxf(s[i][2], s[i][3]));
#pragma unroll
            for (int w = 1; w < 16; w <<= 1)
                rm = fmaxf(rm, __shfl_xor_sync(0xFFFFFFFFu, rm, w, 16));
            float mn = fmaxf(m_i[i], rm);
            float alpha = __expf(m_i[i] - mn);
            float rs = 0.0f;
#pragma unroll
            for (int j = 0; j < 4; j++) {
                float p = __expf(s[i][j] - mn);
                s[i][j] = p;
                rs += p;
            }
#pragma unroll
            for (int w = 1; w < 16; w <<= 1)
                rs += __shfl_xor_sync(0xFFFFFFFFu, rs, w, 16);
            l_i[i] = l_i[i] * alpha + rs;
            m_i[i] = mn;
#pragma unroll
            for (int j = 0; j < 4; j++) o[i][j] *= alpha;
            // write P transposed (k-major) for the O-gemm
#pragma unroll
            for (int j = 0; j < 4; j++)
                PsT[(tx*4 + j)*PAD + ty*4 + i] = s[i][j];
        }
        __syncthreads();

        // O += P @ V
#pragma unroll 8
        for (int kk = 0; kk < 64; kk++) {
            float4 a4 = *(const float4*)&PsT[kk*PAD + ty*4];
            float4 b4 = *(const float4*)&Vs[kk*64 + tx*4];
            float a[4] = {a4.x, a4.y, a4.z, a4.w};
            float b[4] = {b4.x, b4.y, b4.z, b4.w};
#pragma unroll
            for (int i = 0; i < 4; i++)
#pragma unroll
                for (int j = 0; j < 4; j++)
                    o[i][j] = fmaf(a[i], b[j], o[i][j]);
        }
    }

    // Epilogue: normalize, write ctx[b, s, h*64 + d]
    const int b = bh >> 4, h = bh & 15;
#pragma unroll
    for (int i = 0; i < 4; i++) {
        float inv = 1.0f / l_i[i];
        int srow = qbase + ty*4 + i;
        float4 r4;
        r4.x = o[i][0] * inv;
        r4.y = o[i][1] * inv;
        r4.z = o[i][2] * inv;
        r4.w = o[i][3] * inv;
        *(float4*)&ctx[((size_t)(b*SEQ + srow)) * D_MODEL + h*HDIM + tx*4] = r4;
    }
}

// ---------------------------------------------------------------------------
extern "C" void kernel_launch(void* const* d_in, const int* in_sizes, int n_in,
                              void* d_out, int out_size)
{
    const float* X  = (const float*)d_in[0];
    const float* Wq = (const float*)d_in[1];
    const float* Wk = (const float*)d_in[2];
    const float* Wv = (const float*)d_in[3];
    const float* Wo = (const float*)d_in[4];
    const float* bo = (const float*)d_in[5];
    float* out = (float*)d_out;

    float *pq, *pk, *pv, *pctx;
    cudaGetSymbolAddress((void**)&pq,  g_q);
    cudaGetSymbolAddress((void**)&pk,  g_k);
    cudaGetSymbolAddress((void**)&pv,  g_v);
    cudaGetSymbolAddress((void**)&pctx, g_ctx);

    dim3 ggrid(D_MODEL/128, MROWS/128);   // (8, 32)
    gemm128<<<ggrid, 256>>>(X, Wq, nullptr, pq, MROWS, D_MODEL, D_MODEL);
    gemm128<<<ggrid, 256>>>(X, Wk, nullptr, pk, MROWS, D_MODEL, D_MODEL);
    gemm128<<<ggrid, 256>>>(X, Wv, nullptr, pv, MROWS, D_MODEL, D_MODEL);

    const int smem = (3*64*PAD + 64*64) * (int)sizeof(float);  // 68608 B
    cudaFuncSetAttribute(attn64, cudaFuncAttributeMaxDynamicSharedMemorySize, smem);
    dim3 agrid(SEQ/64, BATCH*HEADS);      // (32, 32)
    attn64<<<agrid, 256, smem>>>(pq, pk, pv, pctx);

    gemm128<<<ggrid, 256>>>(pctx, Wo, bo, out, MROWS, D_MODEL, D_MODEL);
}

// round 3
// speedup vs baseline: 1.6229x; 1.6229x over previous
#include <cuda_runtime.h>
#include <math.h>
#include <stdint.h>

#define D_MODEL 1024
#define SEQ     2048
#define BATCH   2
#define HEADS   16
#define HDIM    64
#define MROWS   (BATCH*SEQ)   // 4096
#define PAD     68            // attn smem pitch

// GEMM tiling
#define BK    32
#define PADK  36              // smem row pitch (floats); 36*4=144B, 16B-aligned rows
#define NIT   (D_MODEL/BK)    // 32
#define STG_F (128*PADK)      // floats per stage per operand

// Scratch (no allocations allowed)
__device__ float g_q[(size_t)MROWS * D_MODEL];
__device__ float g_k[(size_t)MROWS * D_MODEL];
__device__ float g_v[(size_t)MROWS * D_MODEL];
__device__ float g_ctx[(size_t)MROWS * D_MODEL];

// ---------------- PTX helpers ----------------
__device__ __forceinline__ uint32_t smem_u32(const void* p){
  uint32_t a;
  asm("{ .reg .u64 t; cvta.to.shared.u64 t, %1; cvt.u32.u64 %0, t; }" : "=r"(a) : "l"(p));
  return a;
}
__device__ __forceinline__ void cp_async16(uint32_t s, const void* g){
  asm volatile("cp.async.cg.shared.global [%0], [%1], 16;" :: "r"(s), "l"(g) : "memory");
}
__device__ __forceinline__ void cp_commit(){ asm volatile("cp.async.commit_group;" ::: "memory"); }
__device__ __forceinline__ void cp_wait1(){ asm volatile("cp.async.wait_group 1;" ::: "memory"); }
__device__ __forceinline__ void cp_wait0(){ asm volatile("cp.async.wait_group 0;" ::: "memory"); }
__device__ __forceinline__ uint32_t f2tf32(float f){
  uint32_t u;
  asm("cvt.rna.tf32.f32 %0, %1;" : "=r"(u) : "f"(f));
  return u;
}
__device__ __forceinline__ void mma_tf32(float* c, const uint32_t* a, const uint32_t* b){
  asm volatile(
    "mma.sync.aligned.m16n8k8.row.col.f32.tf32.tf32.f32 "
    "{%0,%1,%2,%3}, {%4,%5,%6,%7}, {%8,%9}, {%0,%1,%2,%3};"
    : "+f"(c[0]), "+f"(c[1]), "+f"(c[2]), "+f"(c[3])
    : "r"(a[0]), "r"(a[1]), "r"(a[2]), "r"(a[3]), "r"(b[0]), "r"(b[1]));
}

// ---------------------------------------------------------------------------
// tf32 mma.sync GEMM: C[4096,1024] = A[4096,1024] @ W[1024,1024]^T (+bias)
// 128x128x32 tiles, 256 threads = 8 warps (2x4), warp tile 64x32 (4x4 mma of
// m16n8k8). Double-buffered cp.async. blockIdx.z selects (W,C) so Q/K/V fuse.
// ---------------------------------------------------------------------------
static __device__ __forceinline__ void load_stage(
    uint32_t sA, uint32_t sW, const float* A, const float* W,
    int m0, int n0, int k0, int tid)
{
#pragma unroll
  for (int u = 0; u < 4; u++){
    int q = tid + u*256;          // 0..1023 16B-chunks
    int r = q >> 3, c4 = q & 7;   // row, float4-col
    uint32_t so = (uint32_t)(r*PADK + c4*4) * 4u;
    cp_async16(sA + so, A + (size_t)(m0 + r)*D_MODEL + k0 + c4*4);
    cp_async16(sW + so, W + (size_t)(n0 + r)*D_MODEL + k0 + c4*4);
  }
}

__global__ __launch_bounds__(256) void gemm_mma(
    const float* __restrict__ A,
    const float* __restrict__ Wa, const float* __restrict__ Wb, const float* __restrict__ Wc,
    float* __restrict__ Ca, float* __restrict__ Cb, float* __restrict__ Cc,
    const float* __restrict__ bias)
{
  const float* W = (blockIdx.z == 0) ? Wa : (blockIdx.z == 1) ? Wb : Wc;
  float*       C = (blockIdx.z == 0) ? Ca : (blockIdx.z == 1) ? Cb : Cc;

  extern __shared__ float smf[];
  float* As = smf;                  // [2][128][PADK]
  float* Ws = smf + 2*STG_F;        // [2][128][PADK]
  const uint32_t sAu = smem_u32(As);
  const uint32_t sWu = smem_u32(Ws);

  const int tid  = threadIdx.x;
  const int wid  = tid >> 5;
  const int lane = tid & 31;
  const int g    = lane >> 2;       // group id (0..7)
  const int t4   = lane & 3;        // thread-in-group
  const int wm   = wid >> 2;        // 0..1  (row 64-block)
  const int wn   = wid & 3;         // 0..3  (col 32-block)
  const int m0   = blockIdx.y * 128;
  const int n0   = blockIdx.x * 128;

  float c[4][4][4];                 // [mt][nt][reg]
#pragma unroll
  for (int i = 0; i < 4; i++)
#pragma unroll
    for (int j = 0; j < 4; j++)
#pragma unroll
      for (int r = 0; r < 4; r++) c[i][j][r] = 0.0f;

  load_stage(sAu, sWu, A, W, m0, n0, 0, tid);
  cp_commit();

  for (int it = 0; it < NIT; it++){
    const int s = it & 1;
    if (it + 1 < NIT){
      const int sn = s ^ 1;
      load_stage(sAu + sn*STG_F*4, sWu + sn*STG_F*4, A, W, m0, n0, (it+1)*BK, tid);
      cp_commit();
      cp_wait1();
    } else {
      cp_wait0();
    }
    __syncthreads();

    const float* as = As + s*STG_F;
    const float* ws = Ws + s*STG_F;
#pragma unroll
    for (int ks = 0; ks < 4; ks++){
      const int k0 = ks*8;
      uint32_t af[4][4], bf[4][2];
#pragma unroll
      for (int mt = 0; mt < 4; mt++){
        const float* p = as + (wm*64 + mt*16 + g)*PADK + k0 + t4;
        af[mt][0] = f2tf32(p[0]);
        af[mt][1] = f2tf32(p[8*PADK]);
        af[mt][2] = f2tf32(p[4]);
        af[mt][3] = f2tf32(p[8*PADK + 4]);
      }
#pragma unroll
      for (int nt = 0; nt < 4; nt++){
        const float* p = ws + (wn*32 + nt*8 + g)*PADK + k0 + t4;
        bf[nt][0] = f2tf32(p[0]);
        bf[nt][1] = f2tf32(p[4]);
      }
#pragma unroll
      for (int mt = 0; mt < 4; mt++)
#pragma unroll
        for (int nt = 0; nt < 4; nt++)
          mma_tf32(c[mt][nt], af[mt], bf[nt]);
    }
    __syncthreads();
  }

  // Epilogue: C frag c0:(g, 2t) c1:(g, 2t+1) c2:(g+8, 2t) c3:(g+8, 2t+1)
#pragma unroll
  for (int mt = 0; mt < 4; mt++){
    const int r0 = m0 + wm*64 + mt*16 + g;
#pragma unroll
    for (int nt = 0; nt < 4; nt++){
      const int col = n0 + wn*32 + nt*8 + t4*2;
      float b0 = 0.0f, b1 = 0.0f;
      if (bias){ b0 = bias[col]; b1 = bias[col+1]; }
      float2 v0 = make_float2(c[mt][nt][0] + b0, c[mt][nt][1] + b1);
      float2 v1 = make_float2(c[mt][nt][2] + b0, c[mt][nt][3] + b1);
      *(float2*)&C[(size_t)r0       * D_MODEL + col] = v0;
      *(float2*)&C[(size_t)(r0 + 8) * D_MODEL + col] = v1;
    }
  }
}

// ---------------------------------------------------------------------------
// Flash attention per (b,h) — unchanged (verified correct, 692us).
// ---------------------------------------------------------------------------
__global__ __launch_bounds__(256) void attn64(
    const float* __restrict__ Qg, const float* __restrict__ Kg,
    const float* __restrict__ Vg, float* __restrict__ ctx)
{
    extern __shared__ float sm[];
    float* QsT = sm;
    float* KsT = QsT + 64*PAD;
    float* PsT = KsT + 64*PAD;
    float* Vs  = PsT + 64*PAD;

    const int tid = threadIdx.x;
    const int tx = tid & 15, ty = tid >> 4;
    const int bh = blockIdx.y;
    const int qt = blockIdx.x;
    const int qbase = qt * 64;
    const float* Qh = Qg + (size_t)bh * SEQ * HDIM;
    const float* Kh = Kg + (size_t)bh * SEQ * HDIM;
    const float* Vh = Vg + (size_t)bh * SEQ * HDIM;
    const float scale = 1.0f / 64.0f;

#pragma unroll
    for (int u = 0; u < 4; u++) {
        int f = tid + 256*u;
        int r = f >> 4, cc = (f & 15) << 2;
        float4 q4 = *(const float4*)(Qh + (size_t)(qbase + r)*HDIM + cc);
        QsT[(cc+0)*PAD + r] = q4.x * scale;
        QsT[(cc+1)*PAD + r] = q4.y * scale;
        QsT[(cc+2)*PAD + r] = q4.z * scale;
        QsT[(cc+3)*PAD + r] = q4.w * scale;
    }

    float m_i[4], l_i[4], o[4][4];
#pragma unroll
    for (int i = 0; i < 4; i++) {
        m_i[i] = -1e30f; l_i[i] = 0.0f;
#pragma unroll
        for (int j = 0; j < 4; j++) o[i][j] = 0.0f;
    }

    for (int kt = 0; kt <= qt; kt++) {
        const int kbase = kt * 64;
        __syncthreads();
#pragma unroll
        for (int u = 0; u < 4; u++) {
            int f = tid + 256*u;
            int r = f >> 4, cc = (f & 15) << 2;
            float4 k4 = *(const float4*)(Kh + (size_t)(kbase + r)*HDIM + cc);
            KsT[(cc+0)*PAD + r] = k4.x;
            KsT[(cc+1)*PAD + r] = k4.y;
            KsT[(cc+2)*PAD + r] = k4.z;
            KsT[(cc+3)*PAD + r] = k4.w;
            float4 v4 = *(const float4*)(Vh + (size_t)(kbase + r)*HDIM + cc);
            *(float4*)&Vs[r*64 + cc] = v4;
        }
        __syncthreads();

        float s[4][4];
#pragma unroll
        for (int i = 0; i < 4; i++)
#pragma unroll
            for (int j = 0; j < 4; j++) s[i][j] = 0.0f;
#pragma unroll 8
        for (int d = 0; d < 64; d++) {
            float4 a4 = *(const float4*)&QsT[d*PAD + ty*4];
            float4 b4 = *(const float4*)&KsT[d*PAD + tx*4];
            float a[4] = {a4.x, a4.y, a4.z, a4.w};
            float b[4] = {b4.x, b4.y, b4.z, b4.w};
#pragma unroll
            for (int i = 0; i < 4; i++)
#pragma unroll
                for (int j = 0; j < 4; j++)
                    s[i][j] = fmaf(a[i], b[j], s[i][j]);
        }

        if (kt == qt) {
#pragma unroll
            for (int i = 0; i < 4; i++)
#pragma unroll
                for (int j = 0; j < 4; j++)
                    if (tx*4 + j > ty*4 + i) s[i][j] = -1e30f;
        }

#pragma unroll
        for (int i = 0; i < 4; i++) {
            float rm = fmaxf(fmaxf(s[i][0], s[i][1]), fmaxf(s[i][2], s[i][3]));
#pragma unroll
            for (int w = 1; w < 16; w <<= 1)
                rm = fmaxf(rm, __shfl_xor_sync(0xFFFFFFFFu, rm, w, 16));
            float mn = fmaxf(m_i[i], rm);
            float alpha = __expf(m_i[i] - mn);
            float rs = 0.0f;
#pragma unroll
            for (int j = 0; j < 4; j++) {
                float p = __expf(s[i][j] - mn);
                s[i][j] = p;
                rs += p;
            }
#pragma unroll
            for (int w = 1; w < 16; w <<= 1)
                rs += __shfl_xor_sync(0xFFFFFFFFu, rs, w, 16);
            l_i[i] = l_i[i] * alpha + rs;
            m_i[i] = mn;
#pragma unroll
            for (int j = 0; j < 4; j++) o[i][j] *= alpha;
#pragma unroll
            for (int j = 0; j < 4; j++)
                PsT[(tx*4 + j)*PAD + ty*4 + i] = s[i][j];
        }
        __syncthreads();

#pragma unroll 8
        for (int kk = 0; kk < 64; kk++) {
            float4 a4 = *(const float4*)&PsT[kk*PAD + ty*4];
            float4 b4 = *(const float4*)&Vs[kk*64 + tx*4];
            float a[4] = {a4.x, a4.y, a4.z, a4.w};
            float b[4] = {b4.x, b4.y, b4.z, b4.w};
#pragma unroll
            for (int i = 0; i < 4; i++)
#pragma unroll
                for (int j = 0; j < 4; j++)
                    o[i][j] = fmaf(a[i], b[j], o[i][j]);
        }
    }

    const int b = bh >> 4, h = bh & 15;
#pragma unroll
    for (int i = 0; i < 4; i++) {
        float inv = 1.0f / l_i[i];
        int srow = qbase + ty*4 + i;
        float4 r4;
        r4.x = o[i][0] * inv;
        r4.y = o[i][1] * inv;
        r4.z = o[i][2] * inv;
        r4.w = o[i][3] * inv;
        *(float4*)&ctx[((size_t)(b*SEQ + srow)) * D_MODEL + h*HDIM + tx*4] = r4;
    }
}

// ---------------------------------------------------------------------------
extern "C" void kernel_launch(void* const* d_in, const int* in_sizes, int n_in,
                              void* d_out, int out_size)
{
    const float* X  = (const float*)d_in[0];
    const float* Wq = (const float*)d_in[1];
    const float* Wk = (const float*)d_in[2];
    const float* Wv = (const float*)d_in[3];
    const float* Wo = (const float*)d_in[4];
    const float* bo = (const float*)d_in[5];
    float* out = (float*)d_out;

    float *pq, *pk, *pv, *pctx;
    cudaGetSymbolAddress((void**)&pq,  g_q);
    cudaGetSymbolAddress((void**)&pk,  g_k);
    cudaGetSymbolAddress((void**)&pv,  g_v);
    cudaGetSymbolAddress((void**)&pctx, g_ctx);

    const int gsmem = 4 * STG_F * (int)sizeof(float);   // 73728B
    cudaFuncSetAttribute(gemm_mma, cudaFuncAttributeMaxDynamicSharedMemorySize, gsmem);

    // Q,K,V projections fused via blockIdx.z
    gemm_mma<<<dim3(8, 32, 3), 256, gsmem>>>(X, Wq, Wk, Wv, pq, pk, pv, nullptr);

    const int asmem = (3*64*PAD + 64*64) * (int)sizeof(float);
    cudaFuncSetAttribute(attn64, cudaFuncAttributeMaxDynamicSharedMemorySize, asmem);
    attn64<<<dim3(SEQ/64, BATCH*HEADS), 256, asmem>>>(pq, pk, pv, pctx);

    // Output projection + bias
    gemm_mma<<<dim3(8, 32, 1), 256, gsmem>>>(pctx, Wo, Wo, Wo, out, out, out, bo);
}

// round 4
// speedup vs baseline: 3.5787x; 2.2052x over previous
#include <cuda_runtime.h>
#include <math.h>
#include <stdint.h>

#define D_MODEL 1024
#define SEQ     2048
#define BATCH   2
#define HEADS   16
#define HDIM    64
#define MROWS   (BATCH*SEQ)   // 4096

// GEMM tiling
#define BK    32
#define PADK  36
#define NIT   (D_MODEL/BK)
#define STG_F (128*PADK)

// Attention tiling
#define KP 68                 // K smem pitch (floats)
#define VP 72                 // V smem pitch (floats)
#define KS_F (64*KP)          // 4352 floats
#define VS_F (64*VP)          // 4608 floats
#define ASTG_F (KS_F + VS_F)  // 8960 floats per stage

// Scratch
__device__ float g_q[(size_t)MROWS * D_MODEL];
__device__ float g_k[(size_t)MROWS * D_MODEL];
__device__ float g_v[(size_t)MROWS * D_MODEL];
__device__ float g_ctx[(size_t)MROWS * D_MODEL];

// ---------------- PTX helpers ----------------
__device__ __forceinline__ uint32_t smem_u32(const void* p){
  uint32_t a;
  asm("{ .reg .u64 t; cvta.to.shared.u64 t, %1; cvt.u32.u64 %0, t; }" : "=r"(a) : "l"(p));
  return a;
}
__device__ __forceinline__ void cp_async16(uint32_t s, const void* g){
  asm volatile("cp.async.cg.shared.global [%0], [%1], 16;" :: "r"(s), "l"(g) : "memory");
}
__device__ __forceinline__ void cp_commit(){ asm volatile("cp.async.commit_group;" ::: "memory"); }
__device__ __forceinline__ void cp_wait1(){ asm volatile("cp.async.wait_group 1;" ::: "memory"); }
__device__ __forceinline__ void cp_wait0(){ asm volatile("cp.async.wait_group 0;" ::: "memory"); }
__device__ __forceinline__ uint32_t f2tf32(float f){
  uint32_t u;
  asm("cvt.rna.tf32.f32 %0, %1;" : "=r"(u) : "f"(f));
  return u;
}
__device__ __forceinline__ void mma_tf32(float* c, const uint32_t* a, const uint32_t* b){
  asm volatile(
    "mma.sync.aligned.m16n8k8.row.col.f32.tf32.tf32.f32 "
    "{%0,%1,%2,%3}, {%4,%5,%6,%7}, {%8,%9}, {%0,%1,%2,%3};"
    : "+f"(c[0]), "+f"(c[1]), "+f"(c[2]), "+f"(c[3])
    : "r"(a[0]), "r"(a[1]), "r"(a[2]), "r"(a[3]), "r"(b[0]), "r"(b[1]));
}

// ---------------------------------------------------------------------------
// tf32 mma.sync GEMM (as R3) + optional tf32 pre-rounding of outputs.
// ---------------------------------------------------------------------------
static __device__ __forceinline__ void load_stage_g(
    uint32_t sA, uint32_t sW, const float* A, const float* W,
    int m0, int n0, int k0, int tid)
{
#pragma unroll
  for (int u = 0; u < 4; u++){
    int q = tid + u*256;
    int r = q >> 3, c4 = q & 7;
    uint32_t so = (uint32_t)(r*PADK + c4*4) * 4u;
    cp_async16(sA + so, A + (size_t)(m0 + r)*D_MODEL + k0 + c4*4);
    cp_async16(sW + so, W + (size_t)(n0 + r)*D_MODEL + k0 + c4*4);
  }
}

__global__ __launch_bounds__(256) void gemm_mma(
    const float* __restrict__ A,
    const float* __restrict__ Wa, const float* __restrict__ Wb, const float* __restrict__ Wc,
    float* __restrict__ Ca, float* __restrict__ Cb, float* __restrict__ Cc,
    const float* __restrict__ bias, int round_tf32)
{
  const float* W = (blockIdx.z == 0) ? Wa : (blockIdx.z == 1) ? Wb : Wc;
  float*       C = (blockIdx.z == 0) ? Ca : (blockIdx.z == 1) ? Cb : Cc;

  extern __shared__ float smf[];
  float* As = smf;
  float* Ws = smf + 2*STG_F;
  const uint32_t sAu = smem_u32(As);
  const uint32_t sWu = smem_u32(Ws);

  const int tid  = threadIdx.x;
  const int wid  = tid >> 5;
  const int lane = tid & 31;
  const int g    = lane >> 2;
  const int t4   = lane & 3;
  const int wm   = wid >> 2;
  const int wn   = wid & 3;
  const int m0   = blockIdx.y * 128;
  const int n0   = blockIdx.x * 128;

  float c[4][4][4];
#pragma unroll
  for (int i = 0; i < 4; i++)
#pragma unroll
    for (int j = 0; j < 4; j++)
#pragma unroll
      for (int r = 0; r < 4; r++) c[i][j][r] = 0.0f;

  load_stage_g(sAu, sWu, A, W, m0, n0, 0, tid);
  cp_commit();

  for (int it = 0; it < NIT; it++){
    const int s = it & 1;
    if (it + 1 < NIT){
      const int sn = s ^ 1;
      load_stage_g(sAu + sn*STG_F*4, sWu + sn*STG_F*4, A, W, m0, n0, (it+1)*BK, tid);
      cp_commit();
      cp_wait1();
    } else {
      cp_wait0();
    }
    __syncthreads();

    const float* as = As + s*STG_F;
    const float* ws = Ws + s*STG_F;
#pragma unroll
    for (int ks = 0; ks < 4; ks++){
      const int k0 = ks*8;
      uint32_t af[4][4], bf[4][2];
#pragma unroll
      for (int mt = 0; mt < 4; mt++){
        const float* p = as + (wm*64 + mt*16 + g)*PADK + k0 + t4;
        af[mt][0] = f2tf32(p[0]);
        af[mt][1] = f2tf32(p[8*PADK]);
        af[mt][2] = f2tf32(p[4]);
        af[mt][3] = f2tf32(p[8*PADK + 4]);
      }
#pragma unroll
      for (int nt = 0; nt < 4; nt++){
        const float* p = ws + (wn*32 + nt*8 + g)*PADK + k0 + t4;
        bf[nt][0] = f2tf32(p[0]);
        bf[nt][1] = f2tf32(p[4]);
      }
#pragma unroll
      for (int mt = 0; mt < 4; mt++)
#pragma unroll
        for (int nt = 0; nt < 4; nt++)
          mma_tf32(c[mt][nt], af[mt], bf[nt]);
    }
    __syncthreads();
  }

#pragma unroll
  for (int mt = 0; mt < 4; mt++){
    const int r0 = m0 + wm*64 + mt*16 + g;
#pragma unroll
    for (int nt = 0; nt < 4; nt++){
      const int col = n0 + wn*32 + nt*8 + t4*2;
      float b0 = 0.0f, b1 = 0.0f;
      if (bias){ b0 = bias[col]; b1 = bias[col+1]; }
      float v[4];
      v[0] = c[mt][nt][0] + b0; v[1] = c[mt][nt][1] + b1;
      v[2] = c[mt][nt][2] + b0; v[3] = c[mt][nt][3] + b1;
      if (round_tf32){
#pragma unroll
        for (int r = 0; r < 4; r++) v[r] = __uint_as_float(f2tf32(v[r]));
      }
      *(float2*)&C[(size_t)r0       * D_MODEL + col] = make_float2(v[0], v[1]);
      *(float2*)&C[(size_t)(r0 + 8) * D_MODEL + col] = make_float2(v[2], v[3]);
    }
  }
}

// ---------------------------------------------------------------------------
// mma.sync tf32 flash attention.
// CTA: 256 thr / 8 warps; q-tile 128 rows (warp w -> rows w*16..w*16+15);
// k-tile 64 keys; hd=64. q/k/v are tf32-pre-rounded by the QKV gemm.
// ---------------------------------------------------------------------------
static __device__ __forceinline__ void load_kv(
    uint32_t sb, int stage, const float* Kt, const float* Vt, int tid)
{
  const uint32_t base = sb + (uint32_t)stage * ASTG_F * 4u;
#pragma unroll
  for (int u = 0; u < 4; u++){
    int idx = tid + u*256;
    int r = idx >> 4, c = (idx & 15) * 4;
    cp_async16(base + (uint32_t)(r*KP + c)*4u, Kt + r*HDIM + c);
    cp_async16(base + (uint32_t)(KS_F + r*VP + c)*4u, Vt + r*HDIM + c);
  }
}

__global__ __launch_bounds__(256) void attn_mma(
    const float* __restrict__ Qg, const float* __restrict__ Kg,
    const float* __restrict__ Vg, float* __restrict__ ctx)
{
  extern __shared__ float smf[];
  const uint32_t sb = smem_u32(smf);

  const int tid  = threadIdx.x;
  const int wid  = tid >> 5;
  const int lane = tid & 31;
  const int g    = lane >> 2;
  const int t4   = lane & 3;
  const int bh   = blockIdx.y;
  const int qt   = (int)gridDim.x - 1 - (int)blockIdx.x;   // heavy tiles first
  const int qbase = qt * 128;

  const float* Qh = Qg + (size_t)bh * SEQ * HDIM;
  const float* Kh = Kg + (size_t)bh * SEQ * HDIM;
  const float* Vh = Vg + (size_t)bh * SEQ * HDIM;

  // ---- Prologue: stage Q tile (scaled by 1/64) through stage-0 smem ----
#pragma unroll
  for (int u = 0; u < 8; u++){
    int idx = tid + u*256;
    int r = idx >> 4, c = (idx & 15) * 4;
    float4 q4 = *(const float4*)(Qh + (size_t)(qbase + r)*HDIM + c);
    q4.x *= 0.015625f; q4.y *= 0.015625f; q4.z *= 0.015625f; q4.w *= 0.015625f;
    float* dst = (r < 64) ? (smf + r*KP + c) : (smf + KS_F + (r-64)*VP + c);
    *(float4*)dst = q4;
  }
  __syncthreads();

  // Q A-fragments in registers (bits already tf32-clean; 1/64 is exact scale)
  uint32_t qa[8][4];
  {
    const int r0 = wid*16 + g;
    const float* q0 = (r0 < 64) ? (smf + r0*KP) : (smf + KS_F + (r0-64)*VP);
    const int pit = (r0 < 64) ? KP : VP;
#pragma unroll
    for (int kb = 0; kb < 8; kb++){
      const int c = 8*kb + t4;
      qa[kb][0] = __float_as_uint(q0[c]);
      qa[kb][1] = __float_as_uint(q0[8*pit + c]);
      qa[kb][2] = __float_as_uint(q0[c + 4]);
      qa[kb][3] = __float_as_uint(q0[8*pit + c + 4]);
    }
  }
  __syncthreads();

  float oc[8][4];
#pragma unroll
  for (int nb = 0; nb < 8; nb++)
#pragma unroll
    for (int r = 0; r < 4; r++) oc[nb][r] = 0.0f;
  float m0 = -1e30f, m1 = -1e30f, l0 = 0.0f, l1 = 0.0f;

  const int nkt = 2*qt + 2;
  load_kv(sb, 0, Kh, Vh, tid);
  cp_commit();

  const int grow0 = qbase + wid*16 + g;
  const int grow1 = grow0 + 8;
  const int src0 = (lane & ~3) | (t4 >> 1);
  const int src1 = src0 + 2;
  const int odd  = t4 & 1;

  for (int ki = 0; ki < nkt; ki++){
    const int s = ki & 1;
    cp_wait0();
    __syncthreads();
    if (ki + 1 < nkt){
      load_kv(sb, s ^ 1, Kh + (size_t)(ki+1)*64*HDIM, Vh + (size_t)(ki+1)*64*HDIM, tid);
      cp_commit();
    }
    const float* ksm = smf + s*ASTG_F;
    const float* vsm = ksm + KS_F;

    // ---- S = Q @ K^T ----
    float sc[8][4];
#pragma unroll
    for (int nb = 0; nb < 8; nb++)
#pragma unroll
      for (int r = 0; r < 4; r++) sc[nb][r] = 0.0f;
#pragma unroll
    for (int kb = 0; kb < 8; kb++){
#pragma unroll
      for (int nb = 0; nb < 8; nb++){
        const float* kp = ksm + (8*nb + g)*KP + 8*kb + t4;
        uint32_t b[2];
        b[0] = __float_as_uint(kp[0]);
        b[1] = __float_as_uint(kp[4]);
        mma_tf32(sc[nb], qa[kb], b);
      }
    }

    // ---- causal mask (only diagonal-adjacent tiles) ----
    if (ki >= 2*qt){
      const int cb = ki*64 + 2*t4;
#pragma unroll
      for (int nb = 0; nb < 8; nb++){
        const int c0 = cb + 8*nb, c1 = c0 + 1;
        if (c0 > grow0) sc[nb][0] = -1e30f;
        if (c1 > grow0) sc[nb][1] = -1e30f;
        if (c0 > grow1) sc[nb][2] = -1e30f;
        if (c1 > grow1) sc[nb][3] = -1e30f;
      }
    }

    // ---- online softmax (rows quad-local) ----
    float mx0 = -1e30f, mx1 = -1e30f;
#pragma unroll
    for (int nb = 0; nb < 8; nb++){
      mx0 = fmaxf(mx0, fmaxf(sc[nb][0], sc[nb][1]));
      mx1 = fmaxf(mx1, fmaxf(sc[nb][2], sc[nb][3]));
    }
    mx0 = fmaxf(mx0, __shfl_xor_sync(0xffffffffu, mx0, 1));
    mx0 = fmaxf(mx0, __shfl_xor_sync(0xffffffffu, mx0, 2));
    mx1 = fmaxf(mx1, __shfl_xor_sync(0xffffffffu, mx1, 1));
    mx1 = fmaxf(mx1, __shfl_xor_sync(0xffffffffu, mx1, 2));
    const float mn0 = fmaxf(m0, mx0), mn1 = fmaxf(m1, mx1);
    const float al0 = __expf(m0 - mn0), al1 = __expf(m1 - mn1);
    m0 = mn0; m1 = mn1;

    uint32_t pc[8][4];
    float sum0 = 0.0f, sum1 = 0.0f;
#pragma unroll
    for (int nb = 0; nb < 8; nb++){
      float p0 = __expf(sc[nb][0] - mn0);
      float p1 = __expf(sc[nb][1] - mn0);
      float p2 = __expf(sc[nb][2] - mn1);
      float p3 = __expf(sc[nb][3] - mn1);
      sum0 += p0 + p1; sum1 += p2 + p3;
      pc[nb][0] = f2tf32(p0); pc[nb][1] = f2tf32(p1);
      pc[nb][2] = f2tf32(p2); pc[nb][3] = f2tf32(p3);
    }
    sum0 += __shfl_xor_sync(0xffffffffu, sum0, 1);
    sum0 += __shfl_xor_sync(0xffffffffu, sum0, 2);
    sum1 += __shfl_xor_sync(0xffffffffu, sum1, 1);
    sum1 += __shfl_xor_sync(0xffffffffu, sum1, 2);
    l0 = l0*al0 + sum0; l1 = l1*al1 + sum1;
#pragma unroll
    for (int nb = 0; nb < 8; nb++){
      oc[nb][0] *= al0; oc[nb][1] *= al0;
      oc[nb][2] *= al1; oc[nb][3] *= al1;
    }

    // ---- O += P @ V  (P C-frag -> A-frag via quad shuffles) ----
#pragma unroll
    for (int kb = 0; kb < 8; kb++){
      uint32_t a[4];
      {
        uint32_t v0 = __shfl_sync(0xffffffffu, pc[kb][0], src0);
        uint32_t v1 = __shfl_sync(0xffffffffu, pc[kb][1], src0);
        a[0] = odd ? v1 : v0;
        uint32_t v2 = __shfl_sync(0xffffffffu, pc[kb][2], src0);
        uint32_t v3 = __shfl_sync(0xffffffffu, pc[kb][3], src0);
        a[1] = odd ? v3 : v2;
        uint32_t w0 = __shfl_sync(0xffffffffu, pc[kb][0], src1);
        uint32_t w1 = __shfl_sync(0xffffffffu, pc[kb][1], src1);
        a[2] = odd ? w1 : w0;
        uint32_t w2 = __shfl_sync(0xffffffffu, pc[kb][2], src1);
        uint32_t w3 = __shfl_sync(0xffffffffu, pc[kb][3], src1);
        a[3] = odd ? w3 : w2;
      }
#pragma unroll
      for (int nb = 0; nb < 8; nb++){
        const float* vp = vsm + (8*kb + t4)*VP + 8*nb + g;
        uint32_t b[2];
        b[0] = __float_as_uint(vp[0]);
        b[1] = __float_as_uint(vp[4*VP]);
        mma_tf32(oc[nb], a, b);
      }
    }
  }

  // ---- epilogue: normalize, scatter into ctx[b, s, h*64 + d] ----
  const int b = bh >> 4, h = bh & 15;
  const float inv0 = 1.0f / l0, inv1 = 1.0f / l1;
  float* base0 = ctx + ((size_t)(b*SEQ + grow0 - 0)) * D_MODEL + h*HDIM;
#pragma unroll
  for (int nb = 0; nb < 8; nb++){
    const int col = 8*nb + 2*t4;
    *(float2*)(base0 + col)                    = make_float2(oc[nb][0]*inv0, oc[nb][1]*inv0);
    *(float2*)(base0 + 8*(size_t)D_MODEL + col) = make_float2(oc[nb][2]*inv1, oc[nb][3]*inv1);
  }
}

// ---------------------------------------------------------------------------
extern "C" void kernel_launch(void* const* d_in, const int* in_sizes, int n_in,
                              void* d_out, int out_size)
{
    const float* X  = (const float*)d_in[0];
    const float* Wq = (const float*)d_in[1];
    const float* Wk = (const float*)d_in[2];
    const float* Wv = (const float*)d_in[3];
    const float* Wo = (const float*)d_in[4];
    const float* bo = (const float*)d_in[5];
    float* out = (float*)d_out;

    float *pq, *pk, *pv, *pctx;
    cudaGetSymbolAddress((void**)&pq,  g_q);
    cudaGetSymbolAddress((void**)&pk,  g_k);
    cudaGetSymbolAddress((void**)&pv,  g_v);
    cudaGetSymbolAddress((void**)&pctx, g_ctx);

    const int gsmem = 4 * STG_F * (int)sizeof(float);
    cudaFuncSetAttribute(gemm_mma, cudaFuncAttributeMaxDynamicSharedMemorySize, gsmem);

    // Q,K,V projections (outputs pre-rounded to tf32 bit patterns)
    gemm_mma<<<dim3(8, 32, 3), 256, gsmem>>>(X, Wq, Wk, Wv, pq, pk, pv, nullptr, 1);

    const int asmem = 2 * ASTG_F * (int)sizeof(float);   // 71680 B
    cudaFuncSetAttribute(attn_mma, cudaFuncAttributeMaxDynamicSharedMemorySize, asmem);
    attn_mma<<<dim3(SEQ/128, BATCH*HEADS), 256, asmem>>>(pq, pk, pv, pctx);

    // Output projection + bias (full fp32 output)
    gemm_mma<<<dim3(8, 32, 1), 256, gsmem>>>(pctx, Wo, Wo, Wo, out, out, out, bo, 0);
}

// round 5
// speedup vs baseline: 3.6207x; 1.0117x over previous
#include <cuda_runtime.h>
#include <math.h>
#include <stdint.h>

#define D_MODEL 1024
#define SEQ     2048
#define BATCH   2
#define HEADS   16
#define HDIM    64
#define MROWS   (BATCH*SEQ)   // 4096

// GEMM tiling
#define BK    32
#define PADK  36
#define NIT   (D_MODEL/BK)
#define STG_F (128*PADK)

// Attention tiling
#define KP 68
#define VP 72
#define KS_F (64*KP)
#define VS_F (64*VP)
#define ASTG_F (KS_F + VS_F)

// Scratch (tf32-bit-pattern staging + intermediates)
__device__ float g_q[(size_t)MROWS * D_MODEL];
__device__ float g_k[(size_t)MROWS * D_MODEL];
__device__ float g_v[(size_t)MROWS * D_MODEL];
__device__ float g_ctx[(size_t)MROWS * D_MODEL];
__device__ float g_rx[(size_t)MROWS * D_MODEL];          // rounded X
__device__ float g_rw[4 * (size_t)D_MODEL * D_MODEL];    // rounded Wq,Wk,Wv,Wo

// ---------------- PTX helpers ----------------
__device__ __forceinline__ uint32_t smem_u32(const void* p){
  uint32_t a;
  asm("{ .reg .u64 t; cvta.to.shared.u64 t, %1; cvt.u32.u64 %0, t; }" : "=r"(a) : "l"(p));
  return a;
}
__device__ __forceinline__ void cp_async16(uint32_t s, const void* g){
  asm volatile("cp.async.cg.shared.global [%0], [%1], 16;" :: "r"(s), "l"(g) : "memory");
}
__device__ __forceinline__ void cp_commit(){ asm volatile("cp.async.commit_group;" ::: "memory"); }
__device__ __forceinline__ void cp_wait1(){ asm volatile("cp.async.wait_group 1;" ::: "memory"); }
__device__ __forceinline__ void cp_wait0(){ asm volatile("cp.async.wait_group 0;" ::: "memory"); }
__device__ __forceinline__ uint32_t f2tf32(float f){
  uint32_t u;
  asm("cvt.rna.tf32.f32 %0, %1;" : "=r"(u) : "f"(f));
  return u;
}
__device__ __forceinline__ void mma_tf32(float* c, const uint32_t* a, const uint32_t* b){
  asm volatile(
    "mma.sync.aligned.m16n8k8.row.col.f32.tf32.tf32.f32 "
    "{%0,%1,%2,%3}, {%4,%5,%6,%7}, {%8,%9}, {%0,%1,%2,%3};"
    : "+f"(c[0]), "+f"(c[1]), "+f"(c[2]), "+f"(c[3])
    : "r"(a[0]), "r"(a[1]), "r"(a[2]), "r"(a[3]), "r"(b[0]), "r"(b[1]));
}

// ---------------------------------------------------------------------------
// Prep: round X and the 4 weight matrices to tf32 bit patterns.
// Layout of g_rw: [Wq | Wk | Wv | Wo], 1M floats each.
// ---------------------------------------------------------------------------
__global__ __launch_bounds__(256) void round_prep(
    const float4* __restrict__ X,
    const float4* __restrict__ Wq, const float4* __restrict__ Wk,
    const float4* __restrict__ Wv, const float4* __restrict__ Wo,
    float4* __restrict__ rx, float4* __restrict__ rw)
{
  const int XN = MROWS * D_MODEL / 4;          // 1M float4
  const int WN = D_MODEL * D_MODEL / 4;        // 256K float4 each
  const int total = XN + 4*WN;
  for (int i = blockIdx.x * 256 + threadIdx.x; i < total; i += gridDim.x * 256){
    const float4* src; float4* dst; int j;
    if (i < XN){ src = X; dst = rx; j = i; }
    else {
      int w = (i - XN) / WN;
      j = (i - XN) - w*WN;
      src = (w == 0) ? Wq : (w == 1) ? Wk : (w == 2) ? Wv : Wo;
      dst = rw + (size_t)w * WN;
    }
    float4 v = src[j];
    v.x = __uint_as_float(f2tf32(v.x));
    v.y = __uint_as_float(f2tf32(v.y));
    v.z = __uint_as_float(f2tf32(v.z));
    v.w = __uint_as_float(f2tf32(v.w));
    dst[j] = v;
  }
}

// ---------------------------------------------------------------------------
// tf32 mma.sync GEMM, cvt-free: inputs are pre-rounded tf32 bit patterns.
// ---------------------------------------------------------------------------
static __device__ __forceinline__ void load_stage_g(
    uint32_t sA, uint32_t sW, const float* A, const float* W,
    int m0, int n0, int k0, int tid)
{
#pragma unroll
  for (int u = 0; u < 4; u++){
    int q = tid + u*256;
    int r = q >> 3, c4 = q & 7;
    uint32_t so = (uint32_t)(r*PADK + c4*4) * 4u;
    cp_async16(sA + so, A + (size_t)(m0 + r)*D_MODEL + k0 + c4*4);
    cp_async16(sW + so, W + (size_t)(n0 + r)*D_MODEL + k0 + c4*4);
  }
}

__global__ __launch_bounds__(256) void gemm_mma(
    const float* __restrict__ A,
    const float* __restrict__ Wa, const float* __restrict__ Wb, const float* __restrict__ Wc,
    float* __restrict__ Ca, float* __restrict__ Cb, float* __restrict__ Cc,
    const float* __restrict__ bias, int round_out)
{
  const float* W = (blockIdx.z == 0) ? Wa : (blockIdx.z == 1) ? Wb : Wc;
  float*       C = (blockIdx.z == 0) ? Ca : (blockIdx.z == 1) ? Cb : Cc;

  extern __shared__ float smf[];
  float* As = smf;
  float* Ws = smf + 2*STG_F;
  const uint32_t sAu = smem_u32(As);
  const uint32_t sWu = smem_u32(Ws);

  const int tid  = threadIdx.x;
  const int wid  = tid >> 5;
  const int lane = tid & 31;
  const int g    = lane >> 2;
  const int t4   = lane & 3;
  const int wm   = wid >> 2;
  const int wn   = wid & 3;
  const int m0   = blockIdx.y * 128;
  const int n0   = blockIdx.x * 128;

  float c[4][4][4];
#pragma unroll
  for (int i = 0; i < 4; i++)
#pragma unroll
    for (int j = 0; j < 4; j++)
#pragma unroll
      for (int r = 0; r < 4; r++) c[i][j][r] = 0.0f;

  load_stage_g(sAu, sWu, A, W, m0, n0, 0, tid);
  cp_commit();

  for (int it = 0; it < NIT; it++){
    const int s = it & 1;
    if (it + 1 < NIT){
      const int sn = s ^ 1;
      load_stage_g(sAu + sn*STG_F*4, sWu + sn*STG_F*4, A, W, m0, n0, (it+1)*BK, tid);
      cp_commit();
      cp_wait1();
    } else {
      cp_wait0();
    }
    __syncthreads();

    const uint32_t* as = (const uint32_t*)(As + s*STG_F);
    const uint32_t* ws = (const uint32_t*)(Ws + s*STG_F);
#pragma unroll
    for (int ks = 0; ks < 4; ks++){
      const int k0 = ks*8;
      uint32_t af[4][4], bf[4][2];
#pragma unroll
      for (int mt = 0; mt < 4; mt++){
        const uint32_t* p = as + (wm*64 + mt*16 + g)*PADK + k0 + t4;
        af[mt][0] = p[0];
        af[mt][1] = p[8*PADK];
        af[mt][2] = p[4];
        af[mt][3] = p[8*PADK + 4];
      }
#pragma unroll
      for (int nt = 0; nt < 4; nt++){
        const uint32_t* p = ws + (wn*32 + nt*8 + g)*PADK + k0 + t4;
        bf[nt][0] = p[0];
        bf[nt][1] = p[4];
      }
#pragma unroll
      for (int mt = 0; mt < 4; mt++)
#pragma unroll
        for (int nt = 0; nt < 4; nt++)
          mma_tf32(c[mt][nt], af[mt], bf[nt]);
    }
    __syncthreads();
  }

#pragma unroll
  for (int mt = 0; mt < 4; mt++){
    const int r0 = m0 + wm*64 + mt*16 + g;
#pragma unroll
    for (int nt = 0; nt < 4; nt++){
      const int col = n0 + wn*32 + nt*8 + t4*2;
      float b0 = 0.0f, b1 = 0.0f;
      if (bias){ b0 = bias[col]; b1 = bias[col+1]; }
      float v[4];
      v[0] = c[mt][nt][0] + b0; v[1] = c[mt][nt][1] + b1;
      v[2] = c[mt][nt][2] + b0; v[3] = c[mt][nt][3] + b1;
      if (round_out){
#pragma unroll
        for (int r = 0; r < 4; r++) v[r] = __uint_as_float(f2tf32(v[r]));
      }
      *(float2*)&C[(size_t)r0       * D_MODEL + col] = make_float2(v[0], v[1]);
      *(float2*)&C[(size_t)(r0 + 8) * D_MODEL + col] = make_float2(v[2], v[3]);
    }
  }
}

// ---------------------------------------------------------------------------
// mma.sync tf32 flash attention (R4 structure; epilogue now rounds ctx to
// tf32 bits so the Wo gemm can run cvt-free).
// ---------------------------------------------------------------------------
static __device__ __forceinline__ void load_kv(
    uint32_t sb, int stage, const float* Kt, const float* Vt, int tid)
{
  const uint32_t base = sb + (uint32_t)stage * ASTG_F * 4u;
#pragma unroll
  for (int u = 0; u < 4; u++){
    int idx = tid + u*256;
    int r = idx >> 4, c = (idx & 15) * 4;
    cp_async16(base + (uint32_t)(r*KP + c)*4u, Kt + r*HDIM + c);
    cp_async16(base + (uint32_t)(KS_F + r*VP + c)*4u, Vt + r*HDIM + c);
  }
}

__global__ __launch_bounds__(256) void attn_mma(
    const float* __restrict__ Qg, const float* __restrict__ Kg,
    const float* __restrict__ Vg, float* __restrict__ ctx)
{
  extern __shared__ float smf[];
  const uint32_t sb = smem_u32(smf);

  const int tid  = threadIdx.x;
  const int wid  = tid >> 5;
  const int lane = tid & 31;
  const int g    = lane >> 2;
  const int t4   = lane & 3;
  const int bh   = blockIdx.y;
  const int qt   = (int)gridDim.x - 1 - (int)blockIdx.x;
  const int qbase = qt * 128;

  const float* Qh = Qg + (size_t)bh * SEQ * HDIM;
  const float* Kh = Kg + (size_t)bh * SEQ * HDIM;
  const float* Vh = Vg + (size_t)bh * SEQ * HDIM;

#pragma unroll
  for (int u = 0; u < 8; u++){
    int idx = tid + u*256;
    int r = idx >> 4, c = (idx & 15) * 4;
    float4 q4 = *(const float4*)(Qh + (size_t)(qbase + r)*HDIM + c);
    q4.x *= 0.015625f; q4.y *= 0.015625f; q4.z *= 0.015625f; q4.w *= 0.015625f;
    float* dst = (r < 64) ? (smf + r*KP + c) : (smf + KS_F + (r-64)*VP + c);
    *(float4*)dst = q4;
  }
  __syncthreads();

  uint32_t qa[8][4];
  {
    const int r0 = wid*16 + g;
    const float* q0 = (r0 < 64) ? (smf + r0*KP) : (smf + KS_F + (r0-64)*VP);
    const int pit = (r0 < 64) ? KP : VP;
#pragma unroll
    for (int kb = 0; kb < 8; kb++){
      const int c = 8*kb + t4;
      qa[kb][0] = __float_as_uint(q0[c]);
      qa[kb][1] = __float_as_uint(q0[8*pit + c]);
      qa[kb][2] = __float_as_uint(q0[c + 4]);
      qa[kb][3] = __float_as_uint(q0[8*pit + c + 4]);
    }
  }
  __syncthreads();

  float oc[8][4];
#pragma unroll
  for (int nb = 0; nb < 8; nb++)
#pragma unroll
    for (int r = 0; r < 4; r++) oc[nb][r] = 0.0f;
  float m0 = -1e30f, m1 = -1e30f, l0 = 0.0f, l1 = 0.0f;

  const int nkt = 2*qt + 2;
  load_kv(sb, 0, Kh, Vh, tid);
  cp_commit();

  const int grow0 = qbase + wid*16 + g;
  const int grow1 = grow0 + 8;
  const int src0 = (lane & ~3) | (t4 >> 1);
  const int src1 = src0 + 2;
  const int odd  = t4 & 1;

  for (int ki = 0; ki < nkt; ki++){
    const int s = ki & 1;
    cp_wait0();
    __syncthreads();
    if (ki + 1 < nkt){
      load_kv(sb, s ^ 1, Kh + (size_t)(ki+1)*64*HDIM, Vh + (size_t)(ki+1)*64*HDIM, tid);
      cp_commit();
    }
    const float* ksm = smf + s*ASTG_F;
    const float* vsm = ksm + KS_F;

    float sc[8][4];
#pragma unroll
    for (int nb = 0; nb < 8; nb++)
#pragma unroll
      for (int r = 0; r < 4; r++) sc[nb][r] = 0.0f;
#pragma unroll
    for (int kb = 0; kb < 8; kb++){
#pragma unroll
      for (int nb = 0; nb < 8; nb++){
        const float* kp = ksm + (8*nb + g)*KP + 8*kb + t4;
        uint32_t b[2];
        b[0] = __float_as_uint(kp[0]);
        b[1] = __float_as_uint(kp[4]);
        mma_tf32(sc[nb], qa[kb], b);
      }
    }

    if (ki >= 2*qt){
      const int cb = ki*64 + 2*t4;
#pragma unroll
      for (int nb = 0; nb < 8; nb++){
        const int c0 = cb + 8*nb, c1 = c0 + 1;
        if (c0 > grow0) sc[nb][0] = -1e30f;
        if (c1 > grow0) sc[nb][1] = -1e30f;
        if (c0 > grow1) sc[nb][2] = -1e30f;
        if (c1 > grow1) sc[nb][3] = -1e30f;
      }
    }

    float mx0 = -1e30f, mx1 = -1e30f;
#pragma unroll
    for (int nb = 0; nb < 8; nb++){
      mx0 = fmaxf(mx0, fmaxf(sc[nb][0], sc[nb][1]));
      mx1 = fmaxf(mx1, fmaxf(sc[nb][2], sc[nb][3]));
    }
    mx0 = fmaxf(mx0, __shfl_xor_sync(0xffffffffu, mx0, 1));
    mx0 = fmaxf(mx0, __shfl_xor_sync(0xffffffffu, mx0, 2));
    mx1 = fmaxf(mx1, __shfl_xor_sync(0xffffffffu, mx1, 1));
    mx1 = fmaxf(mx1, __shfl_xor_sync(0xffffffffu, mx1, 2));
    const float mn0 = fmaxf(m0, mx0), mn1 = fmaxf(m1, mx1);
    const float al0 = __expf(m0 - mn0), al1 = __expf(m1 - mn1);
    m0 = mn0; m1 = mn1;

    uint32_t pc[8][4];
    float sum0 = 0.0f, sum1 = 0.0f;
#pragma unroll
    for (int nb = 0; nb < 8; nb++){
      float p0 = __expf(sc[nb][0] - mn0);
      float p1 = __expf(sc[nb][1] - mn0);
      float p2 = __expf(sc[nb][2] - mn1);
      float p3 = __expf(sc[nb][3] - mn1);
      sum0 += p0 + p1; sum1 += p2 + p3;
      pc[nb][0] = f2tf32(p0); pc[nb][1] = f2tf32(p1);
      pc[nb][2] = f2tf32(p2); pc[nb][3] = f2tf32(p3);
    }
    sum0 += __shfl_xor_sync(0xffffffffu, sum0, 1);
    sum0 += __shfl_xor_sync(0xffffffffu, sum0, 2);
    sum1 += __shfl_xor_sync(0xffffffffu, sum1, 1);
    sum1 += __shfl_xor_sync(0xffffffffu, sum1, 2);
    l0 = l0*al0 + sum0; l1 = l1*al1 + sum1;
#pragma unroll
    for (int nb = 0; nb < 8; nb++){
      oc[nb][0] *= al0; oc[nb][1] *= al0;
      oc[nb][2] *= al1; oc[nb][3] *= al1;
    }

#pragma unroll
    for (int kb = 0; kb < 8; kb++){
      uint32_t a[4];
      {
        uint32_t v0 = __shfl_sync(0xffffffffu, pc[kb][0], src0);
        uint32_t v1 = __shfl_sync(0xffffffffu, pc[kb][1], src0);
        a[0] = odd ? v1 : v0;
        uint32_t v2 = __shfl_sync(0xffffffffu, pc[kb][2], src0);
        uint32_t v3 = __shfl_sync(0xffffffffu, pc[kb][3], src0);
        a[1] = odd ? v3 : v2;
        uint32_t w0 = __shfl_sync(0xffffffffu, pc[kb][0], src1);
        uint32_t w1 = __shfl_sync(0xffffffffu, pc[kb][1], src1);
        a[2] = odd ? w1 : w0;
        uint32_t w2 = __shfl_sync(0xffffffffu, pc[kb][2], src1);
        uint32_t w3 = __shfl_sync(0xffffffffu, pc[kb][3], src1);
        a[3] = odd ? w3 : w2;
      }
#pragma unroll
      for (int nb = 0; nb < 8; nb++){
        const float* vp = vsm + (8*kb + t4)*VP + 8*nb + g;
        uint32_t b[2];
        b[0] = __float_as_uint(vp[0]);
        b[1] = __float_as_uint(vp[4*VP]);
        mma_tf32(oc[nb], a, b);
      }
    }
  }

  // epilogue: normalize, round to tf32 bits, scatter to ctx[b, s, h*64+d]
  const int b = bh >> 4, h = bh & 15;
  const float inv0 = 1.0f / l0, inv1 = 1.0f / l1;
  float* base0 = ctx + ((size_t)(b*SEQ + grow0)) * D_MODEL + h*HDIM;
#pragma unroll
  for (int nb = 0; nb < 8; nb++){
    const int col = 8*nb + 2*t4;
    float2 v0 = make_float2(__uint_as_float(f2tf32(oc[nb][0]*inv0)),
                            __uint_as_float(f2tf32(oc[nb][1]*inv0)));
    float2 v1 = make_float2(__uint_as_float(f2tf32(oc[nb][2]*inv1)),
                            __uint_as_float(f2tf32(oc[nb][3]*inv1)));
    *(float2*)(base0 + col) = v0;
    *(float2*)(base0 + 8*(size_t)D_MODEL + col) = v1;
  }
}

// ---------------------------------------------------------------------------
extern "C" void kernel_launch(void* const* d_in, const int* in_sizes, int n_in,
                              void* d_out, int out_size)
{
    const float* X  = (const float*)d_in[0];
    const float* Wq = (const float*)d_in[1];
    const float* Wk = (const float*)d_in[2];
    const float* Wv = (const float*)d_in[3];
    const float* Wo = (const float*)d_in[4];
    const float* bo = (const float*)d_in[5];
    float* out = (float*)d_out;

    float *pq, *pk, *pv, *pctx, *prx, *prw;
    cudaGetSymbolAddress((void**)&pq,  g_q);
    cudaGetSymbolAddress((void**)&pk,  g_k);
    cudaGetSymbolAddress((void**)&pv,  g_v);
    cudaGetSymbolAddress((void**)&pctx, g_ctx);
    cudaGetSymbolAddress((void**)&prx, g_rx);
    cudaGetSymbolAddress((void**)&prw, g_rw);

    const size_t WSZ = (size_t)D_MODEL * D_MODEL;
    const float* rWq = prw;
    const float* rWk = prw + WSZ;
    const float* rWv = prw + 2*WSZ;
    const float* rWo = prw + 3*WSZ;

    // 0) round inputs to tf32 bit patterns
    round_prep<<<592, 256>>>((const float4*)X, (const float4*)Wq, (const float4*)Wk,
                             (const float4*)Wv, (const float4*)Wo,
                             (float4*)prx, (float4*)prw);

    const int gsmem = 4 * STG_F * (int)sizeof(float);
    cudaFuncSetAttribute(gemm_mma, cudaFuncAttributeMaxDynamicSharedMemorySize, gsmem);

    // 1) Q,K,V projections (cvt-free; outputs tf32-rounded for attention)
    gemm_mma<<<dim3(8, 32, 3), 256, gsmem>>>(prx, rWq, rWk, rWv, pq, pk, pv, nullptr, 1);

    // 2) attention (ctx written tf32-rounded)
    const int asmem = 2 * ASTG_F * (int)sizeof(float);
    cudaFuncSetAttribute(attn_mma, cudaFuncAttributeMaxDynamicSharedMemorySize, asmem);
    attn_mma<<<dim3(SEQ/128, BATCH*HEADS), 256, asmem>>>(pq, pk, pv, pctx);

    // 3) output projection + bias (cvt-free, fp32 output)
    gemm_mma<<<dim3(8, 32, 1), 256, gsmem>>>(pctx, rWo, rWo, rWo, out, out, out, bo, 0);
}

// round 6
// speedup vs baseline: 3.8451x; 1.0620x over previous
#include <cuda_runtime.h>
#include <math.h>
#include <stdint.h>

#define D_MODEL 1024
#define SEQ     2048
#define BATCH   2
#define HEADS   16
#define HDIM    64
#define MROWS   (BATCH*SEQ)   // 4096

// GEMM tiling
#define BK    32
#define PADK  36
#define NIT   (D_MODEL/BK)
#define STG_F (128*PADK)

// Attention tiling
#define KP 68
#define VP 72
#define KS_F (64*KP)
#define VS_F (64*VP)
#define ASTG_F (KS_F + VS_F)

// Scratch
__device__ float g_q[(size_t)MROWS * D_MODEL];
__device__ float g_k[(size_t)MROWS * D_MODEL];
__device__ float g_v[(size_t)MROWS * D_MODEL];
__device__ float g_ctx[(size_t)MROWS * D_MODEL];
__device__ float g_rx[(size_t)MROWS * D_MODEL];
__device__ float g_rw[4 * (size_t)D_MODEL * D_MODEL];

// ---------------- PTX helpers ----------------
__device__ __forceinline__ uint32_t smem_u32(const void* p){
  uint32_t a;
  asm("{ .reg .u64 t; cvta.to.shared.u64 t, %1; cvt.u32.u64 %0, t; }" : "=r"(a) : "l"(p));
  return a;
}
__device__ __forceinline__ void cp_async16(uint32_t s, const void* g){
  asm volatile("cp.async.cg.shared.global [%0], [%1], 16;" :: "r"(s), "l"(g) : "memory");
}
__device__ __forceinline__ void cp_commit(){ asm volatile("cp.async.commit_group;" ::: "memory"); }
__device__ __forceinline__ void cp_wait1(){ asm volatile("cp.async.wait_group 1;" ::: "memory"); }
__device__ __forceinline__ void cp_wait0(){ asm volatile("cp.async.wait_group 0;" ::: "memory"); }
__device__ __forceinline__ uint32_t f2tf32(float f){
  uint32_t u;
  asm("cvt.rna.tf32.f32 %0, %1;" : "=r"(u) : "f"(f));
  return u;
}
__device__ __forceinline__ void mma_tf32(float* c, const uint32_t* a, const uint32_t* b){
  asm volatile(
    "mma.sync.aligned.m16n8k8.row.col.f32.tf32.tf32.f32 "
    "{%0,%1,%2,%3}, {%4,%5,%6,%7}, {%8,%9}, {%0,%1,%2,%3};"
    : "+f"(c[0]), "+f"(c[1]), "+f"(c[2]), "+f"(c[3])
    : "r"(a[0]), "r"(a[1]), "r"(a[2]), "r"(a[3]), "r"(b[0]), "r"(b[1]));
}
// ldmatrix x4 on f32 data: each 8x8 b16 tile == 8 rows x 4 f32 cols; lane i
// receives f32 (row i/4, col i%4) of its tile — the tf32 fragment layout.
__device__ __forceinline__ void ldsm4(uint32_t* r, uint32_t addr){
  asm volatile("ldmatrix.sync.aligned.m8n8.x4.shared.b16 {%0,%1,%2,%3}, [%4];"
    : "=r"(r[0]), "=r"(r[1]), "=r"(r[2]), "=r"(r[3]) : "r"(addr));
}

// ---------------------------------------------------------------------------
// Prep: round X and the 4 weight matrices to tf32 bit patterns.
// ---------------------------------------------------------------------------
__global__ __launch_bounds__(256) void round_prep(
    const float4* __restrict__ X,
    const float4* __restrict__ Wq, const float4* __restrict__ Wk,
    const float4* __restrict__ Wv, const float4* __restrict__ Wo,
    float4* __restrict__ rx, float4* __restrict__ rw)
{
  const int XN = MROWS * D_MODEL / 4;
  const int WN = D_MODEL * D_MODEL / 4;
  const int total = XN + 4*WN;
  for (int i = blockIdx.x * 256 + threadIdx.x; i < total; i += gridDim.x * 256){
    const float4* src; float4* dst; int j;
    if (i < XN){ src = X; dst = rx; j = i; }
    else {
      int w = (i - XN) / WN;
      j = (i - XN) - w*WN;
      src = (w == 0) ? Wq : (w == 1) ? Wk : (w == 2) ? Wv : Wo;
      dst = rw + (size_t)w * WN;
    }
    float4 v = src[j];
    v.x = __uint_as_float(f2tf32(v.x));
    v.y = __uint_as_float(f2tf32(v.y));
    v.z = __uint_as_float(f2tf32(v.z));
    v.w = __uint_as_float(f2tf32(v.w));
    dst[j] = v;
  }
}

// ---------------------------------------------------------------------------
// tf32 mma.sync GEMM with ldmatrix fragment loads.
// ---------------------------------------------------------------------------
static __device__ __forceinline__ void load_stage_g(
    uint32_t sA, uint32_t sW, const float* A, const float* W,
    int m0, int n0, int k0, int tid)
{
#pragma unroll
  for (int u = 0; u < 4; u++){
    int q = tid + u*256;
    int r = q >> 3, c4 = q & 7;
    uint32_t so = (uint32_t)(r*PADK + c4*4) * 4u;
    cp_async16(sA + so, A + (size_t)(m0 + r)*D_MODEL + k0 + c4*4);
    cp_async16(sW + so, W + (size_t)(n0 + r)*D_MODEL + k0 + c4*4);
  }
}

__global__ __launch_bounds__(256) void gemm_mma(
    const float* __restrict__ A,
    const float* __restrict__ Wa, const float* __restrict__ Wb, const float* __restrict__ Wc,
    float* __restrict__ Ca, float* __restrict__ Cb, float* __restrict__ Cc,
    const float* __restrict__ bias, int round_out)
{
  const float* W = (blockIdx.z == 0) ? Wa : (blockIdx.z == 1) ? Wb : Wc;
  float*       C = (blockIdx.z == 0) ? Ca : (blockIdx.z == 1) ? Cb : Cc;

  extern __shared__ float smf[];
  float* As = smf;
  float* Ws = smf + 2*STG_F;
  const uint32_t sAu = smem_u32(As);
  const uint32_t sWu = smem_u32(Ws);

  const int tid  = threadIdx.x;
  const int wid  = tid >> 5;
  const int lane = tid & 31;
  const int g    = lane >> 2;
  const int t4   = lane & 3;
  const int wm   = wid >> 2;
  const int wn   = wid & 3;
  const int m0   = blockIdx.y * 128;
  const int n0   = blockIdx.x * 128;

  // ldmatrix lane address offsets (bytes, relative to stage base)
  uint32_t a_off[4], b_off[2];
  {
    const int rsub = ((lane >> 3) & 1) * 8 + (lane & 7);   // row within 16-row tile
    const int kca  = (lane >> 4) * 4;                      // A: k col offset (tiles 2,3)
    const int kcb  = ((lane >> 3) & 1) * 4;                // B: k col offset (tiles 1,3)
    const int rsb  = ((lane >> 4) & 1) * 8 + (lane & 7);   // B row within 16
#pragma unroll
    for (int mt = 0; mt < 4; mt++)
      a_off[mt] = (uint32_t)(((wm*64 + mt*16 + rsub)*PADK + kca) * 4);
#pragma unroll
    for (int np = 0; np < 2; np++)
      b_off[np] = (uint32_t)(((wn*32 + np*16 + rsb)*PADK + kcb) * 4);
  }

  float c[4][4][4];
#pragma unroll
  for (int i = 0; i < 4; i++)
#pragma unroll
    for (int j = 0; j < 4; j++)
#pragma unroll
      for (int r = 0; r < 4; r++) c[i][j][r] = 0.0f;

  load_stage_g(sAu, sWu, A, W, m0, n0, 0, tid);
  cp_commit();

  for (int it = 0; it < NIT; it++){
    const int s = it & 1;
    if (it + 1 < NIT){
      const int sn = s ^ 1;
      load_stage_g(sAu + sn*STG_F*4, sWu + sn*STG_F*4, A, W, m0, n0, (it+1)*BK, tid);
      cp_commit();
      cp_wait1();
    } else {
      cp_wait0();
    }
    __syncthreads();

    const uint32_t aBase = sAu + (uint32_t)s*STG_F*4u;
    const uint32_t bBase = sWu + (uint32_t)s*STG_F*4u;
#pragma unroll
    for (int ks = 0; ks < 4; ks++){
      const uint32_t kb = (uint32_t)(ks*8*4);
      uint32_t af[4][4], bf[2][4];
#pragma unroll
      for (int mt = 0; mt < 4; mt++) ldsm4(af[mt], aBase + a_off[mt] + kb);
#pragma unroll
      for (int np = 0; np < 2; np++) ldsm4(bf[np], bBase + b_off[np] + kb);
#pragma unroll
      for (int mt = 0; mt < 4; mt++)
#pragma unroll
        for (int nt = 0; nt < 4; nt++)
          mma_tf32(c[mt][nt], af[mt], &bf[nt >> 1][(nt & 1)*2]);
    }
    __syncthreads();
  }

#pragma unroll
  for (int mt = 0; mt < 4; mt++){
    const int r0 = m0 + wm*64 + mt*16 + g;
#pragma unroll
    for (int nt = 0; nt < 4; nt++){
      const int col = n0 + wn*32 + nt*8 + t4*2;
      float b0 = 0.0f, b1 = 0.0f;
      if (bias){ b0 = bias[col]; b1 = bias[col+1]; }
      float v[4];
      v[0] = c[mt][nt][0] + b0; v[1] = c[mt][nt][1] + b1;
      v[2] = c[mt][nt][2] + b0; v[3] = c[mt][nt][3] + b1;
      if (round_out){
#pragma unroll
        for (int r = 0; r < 4; r++) v[r] = __uint_as_float(f2tf32(v[r]));
      }
      *(float2*)&C[(size_t)r0       * D_MODEL + col] = make_float2(v[0], v[1]);
      *(float2*)&C[(size_t)(r0 + 8) * D_MODEL + col] = make_float2(v[2], v[3]);
    }
  }
}

// ---------------------------------------------------------------------------
// mma.sync tf32 flash attention; K fragments via ldmatrix.
// ---------------------------------------------------------------------------
static __device__ __forceinline__ void load_kv(
    uint32_t sb, int stage, const float* Kt, const float* Vt, int tid)
{
  const uint32_t base = sb + (uint32_t)stage * ASTG_F * 4u;
#pragma unroll
  for (int u = 0; u < 4; u++){
    int idx = tid + u*256;
    int r = idx >> 4, c = (idx & 15) * 4;
    cp_async16(base + (uint32_t)(r*KP + c)*4u, Kt + r*HDIM + c);
    cp_async16(base + (uint32_t)(KS_F + r*VP + c)*4u, Vt + r*HDIM + c);
  }
}

__global__ __launch_bounds__(256) void attn_mma(
    const float* __restrict__ Qg, const float* __restrict__ Kg,
    const float* __restrict__ Vg, float* __restrict__ ctx)
{
  extern __shared__ float smf[];
  const uint32_t sb = smem_u32(smf);

  const int tid  = threadIdx.x;
  const int wid  = tid >> 5;
  const int lane = tid & 31;
  const int g    = lane >> 2;
  const int t4   = lane & 3;
  const int bh   = blockIdx.y;
  const int qt   = (int)gridDim.x - 1 - (int)blockIdx.x;
  const int qbase = qt * 128;

  const float* Qh = Qg + (size_t)bh * SEQ * HDIM;
  const float* Kh = Kg + (size_t)bh * SEQ * HDIM;
  const float* Vh = Vg + (size_t)bh * SEQ * HDIM;

  // K-fragment ldmatrix offsets (bytes, relative to K stage base)
  uint32_t k_off[4];
  {
    const int rsb = ((lane >> 4) & 1) * 8 + (lane & 7);
    const int kcb = ((lane >> 3) & 1) * 4;
#pragma unroll
    for (int np = 0; np < 4; np++)
      k_off[np] = (uint32_t)(((np*16 + rsb)*KP + kcb) * 4);
  }

#pragma unroll
  for (int u = 0; u < 8; u++){
    int idx = tid + u*256;
    int r = idx >> 4, c = (idx & 15) * 4;
    float4 q4 = *(const float4*)(Qh + (size_t)(qbase + r)*HDIM + c);
    q4.x *= 0.015625f; q4.y *= 0.015625f; q4.z *= 0.015625f; q4.w *= 0.015625f;
    float* dst = (r < 64) ? (smf + r*KP + c) : (smf + KS_F + (r-64)*VP + c);
    *(float4*)dst = q4;
  }
  __syncthreads();

  uint32_t qa[8][4];
  {
    const int r0 = wid*16 + g;
    const float* q0 = (r0 < 64) ? (smf + r0*KP) : (smf + KS_F + (r0-64)*VP);
    const int pit = (r0 < 64) ? KP : VP;
#pragma unroll
    for (int kb = 0; kb < 8; kb++){
      const int c = 8*kb + t4;
      qa[kb][0] = __float_as_uint(q0[c]);
      qa[kb][1] = __float_as_uint(q0[8*pit + c]);
      qa[kb][2] = __float_as_uint(q0[c + 4]);
      qa[kb][3] = __float_as_uint(q0[8*pit + c + 4]);
    }
  }
  __syncthreads();

  float oc[8][4];
#pragma unroll
  for (int nb = 0; nb < 8; nb++)
#pragma unroll
    for (int r = 0; r < 4; r++) oc[nb][r] = 0.0f;
  float m0 = -1e30f, m1 = -1e30f, l0 = 0.0f, l1 = 0.0f;

  const int nkt = 2*qt + 2;
  load_kv(sb, 0, Kh, Vh, tid);
  cp_commit();

  const int grow0 = qbase + wid*16 + g;
  const int grow1 = grow0 + 8;
  const int src0 = (lane & ~3) | (t4 >> 1);
  const int src1 = src0 + 2;
  const int odd  = t4 & 1;

  for (int ki = 0; ki < nkt; ki++){
    const int s = ki & 1;
    cp_wait0();
    __syncthreads();
    if (ki + 1 < nkt){
      load_kv(sb, s ^ 1, Kh + (size_t)(ki+1)*64*HDIM, Vh + (size_t)(ki+1)*64*HDIM, tid);
      cp_commit();
    }
    const uint32_t kBase = sb + (uint32_t)s*ASTG_F*4u;
    const float* vsm = smf + s*ASTG_F + KS_F;

    float sc[8][4];
#pragma unroll
    for (int nb = 0; nb < 8; nb++)
#pragma unroll
      for (int r = 0; r < 4; r++) sc[nb][r] = 0.0f;
#pragma unroll
    for (int kb = 0; kb < 8; kb++){
      const uint32_t kcol = (uint32_t)(8*kb*4);
      uint32_t kf[4][4];
#pragma unroll
      for (int np = 0; np < 4; np++) ldsm4(kf[np], kBase + k_off[np] + kcol);
#pragma unroll
      for (int nb = 0; nb < 8; nb++)
        mma_tf32(sc[nb], qa[kb], &kf[nb >> 1][(nb & 1)*2]);
    }

    if (ki >= 2*qt){
      const int cb = ki*64 + 2*t4;
#pragma unroll
      for (int nb = 0; nb < 8; nb++){
        const int c0 = cb + 8*nb, c1 = c0 + 1;
        if (c0 > grow0) sc[nb][0] = -1e30f;
        if (c1 > grow0) sc[nb][1] = -1e30f;
        if (c0 > grow1) sc[nb][2] = -1e30f;
        if (c1 > grow1) sc[nb][3] = -1e30f;
      }
    }

    float mx0 = -1e30f, mx1 = -1e30f;
#pragma unroll
    for (int nb = 0; nb < 8; nb++){
      mx0 = fmaxf(mx0, fmaxf(sc[nb][0], sc[nb][1]));
      mx1 = fmaxf(mx1, fmaxf(sc[nb][2], sc[nb][3]));
    }
    mx0 = fmaxf(mx0, __shfl_xor_sync(0xffffffffu, mx0, 1));
    mx0 = fmaxf(mx0, __shfl_xor_sync(0xffffffffu, mx0, 2));
    mx1 = fmaxf(mx1, __shfl_xor_sync(0xffffffffu, mx1, 1));
    mx1 = fmaxf(mx1, __shfl_xor_sync(0xffffffffu, mx1, 2));
    const float mn0 = fmaxf(m0, mx0), mn1 = fmaxf(m1, mx1);
    const float al0 = __expf(m0 - mn0), al1 = __expf(m1 - mn1);
    m0 = mn0; m1 = mn1;

    uint32_t pc[8][4];
    float sum0 = 0.0f, sum1 = 0.0f;
#pragma unroll
    for (int nb = 0; nb < 8; nb++){
      float p0 = __expf(sc[nb][0] - mn0);
      float p1 = __expf(sc[nb][1] - mn0);
      float p2 = __expf(sc[nb][2] - mn1);
      float p3 = __expf(sc[nb][3] - mn1);
      sum0 += p0 + p1; sum1 += p2 + p3;
      pc[nb][0] = f2tf32(p0); pc[nb][1] = f2tf32(p1);
      pc[nb][2] = f2tf32(p2); pc[nb][3] = f2tf32(p3);
    }
    sum0 += __shfl_xor_sync(0xffffffffu, sum0, 1);
    sum0 += __shfl_xor_sync(0xffffffffu, sum0, 2);
    sum1 += __shfl_xor_sync(0xffffffffu, sum1, 1);
    sum1 += __shfl_xor_sync(0xffffffffu, sum1, 2);
    l0 = l0*al0 + sum0; l1 = l1*al1 + sum1;
#pragma unroll
    for (int nb = 0; nb < 8; nb++){
      oc[nb][0] *= al0; oc[nb][1] *= al0;
      oc[nb][2] *= al1; oc[nb][3] *= al1;
    }

#pragma unroll
    for (int kb = 0; kb < 8; kb++){
      uint32_t a[4];
      {
        uint32_t v0 = __shfl_sync(0xffffffffu, pc[kb][0], src0);
        uint32_t v1 = __shfl_sync(0xffffffffu, pc[kb][1], src0);
        a[0] = odd ? v1 : v0;
        uint32_t v2 = __shfl_sync(0xffffffffu, pc[kb][2], src0);
        uint32_t v3 = __shfl_sync(0xffffffffu, pc[kb][3], src0);
        a[1] = odd ? v3 : v2;
        uint32_t w0 = __shfl_sync(0xffffffffu, pc[kb][0], src1);
        uint32_t w1 = __shfl_sync(0xffffffffu, pc[kb][1], src1);
        a[2] = odd ? w1 : w0;
        uint32_t w2 = __shfl_sync(0xffffffffu, pc[kb][2], src1);
        uint32_t w3 = __shfl_sync(0xffffffffu, pc[kb][3], src1);
        a[3] = odd ? w3 : w2;
      }
#pragma unroll
      for (int nb = 0; nb < 8; nb++){
        const float* vp = vsm + (8*kb + t4)*VP + 8*nb + g;
        uint32_t b[2];
        b[0] = __float_as_uint(vp[0]);
        b[1] = __float_as_uint(vp[4*VP]);
        mma_tf32(oc[nb], a, b);
      }
    }
  }

  const int b = bh >> 4, h = bh & 15;
  const float inv0 = 1.0f / l0, inv1 = 1.0f / l1;
  float* base0 = ctx + ((size_t)(b*SEQ + grow0)) * D_MODEL + h*HDIM;
#pragma unroll
  for (int nb = 0; nb < 8; nb++){
    const int col = 8*nb + 2*t4;
    float2 v0 = make_float2(__uint_as_float(f2tf32(oc[nb][0]*inv0)),
                            __uint_as_float(f2tf32(oc[nb][1]*inv0)));
    float2 v1 = make_float2(__uint_as_float(f2tf32(oc[nb][2]*inv1)),
                            __uint_as_float(f2tf32(oc[nb][3]*inv1)));
    *(float2*)(base0 + col) = v0;
    *(float2*)(base0 + 8*(size_t)D_MODEL + col) = v1;
  }
}

// ---------------------------------------------------------------------------
extern "C" void kernel_launch(void* const* d_in, const int* in_sizes, int n_in,
                              void* d_out, int out_size)
{
    const float* X  = (const float*)d_in[0];
    const float* Wq = (const float*)d_in[1];
    const float* Wk = (const float*)d_in[2];
    const float* Wv = (const float*)d_in[3];
    const float* Wo = (const float*)d_in[4];
    const float* bo = (const float*)d_in[5];
    float* out = (float*)d_out;

    float *pq, *pk, *pv, *pctx, *prx, *prw;
    cudaGetSymbolAddress((void**)&pq,  g_q);
    cudaGetSymbolAddress((void**)&pk,  g_k);
    cudaGetSymbolAddress((void**)&pv,  g_v);
    cudaGetSymbolAddress((void**)&pctx, g_ctx);
    cudaGetSymbolAddress((void**)&prx, g_rx);
    cudaGetSymbolAddress((void**)&prw, g_rw);

    const size_t WSZ = (size_t)D_MODEL * D_MODEL;
    const float* rWq = prw;
    const float* rWk = prw + WSZ;
    const float* rWv = prw + 2*WSZ;
    const float* rWo = prw + 3*WSZ;

    round_prep<<<592, 256>>>((const float4*)X, (const float4*)Wq, (const float4*)Wk,
                             (const float4*)Wv, (const float4*)Wo,
                             (float4*)prx, (float4*)prw);

    const int gsmem = 4 * STG_F * (int)sizeof(float);
    cudaFuncSetAttribute(gemm_mma, cudaFuncAttributeMaxDynamicSharedMemorySize, gsmem);

    gemm_mma<<<dim3(8, 32, 3), 256, gsmem>>>(prx, rWq, rWk, rWv, pq, pk, pv, nullptr, 1);

    const int asmem = 2 * ASTG_F * (int)sizeof(float);
    cudaFuncSetAttribute(attn_mma, cudaFuncAttributeMaxDynamicSharedMemorySize, asmem);
    attn_mma<<<dim3(SEQ/128, BATCH*HEADS), 256, asmem>>>(pq, pk, pv, pctx);

    gemm_mma<<<dim3(8, 32, 1), 256, gsmem>>>(pctx, rWo, rWo, rWo, out, out, out, bo, 0);
}

// round 7
// speedup vs baseline: 6.7759x; 1.7622x over previous
#include <cuda_runtime.h>
#include <cuda_fp16.h>
#include <math.h>
#include <stdint.h>

#define D_MODEL 1024
#define SEQ     2048
#define BATCH   2
#define HEADS   16
#define HDIM    64
#define MROWS   (BATCH*SEQ)   // 4096

// GEMM tiling (fp16 operands): 128x128 tile, K-chunk 64, pitch 72 halves (144B)
#define GP     72
#define GNIT   16
#define STG_H  (128*GP)       // halves per operand per stage (9216)

// Attention: K/V tiles 64x64 fp16, pitch 72 halves; stage = K + V
#define AP     72
#define KVH    (64*AP)        // 4608 halves per operand
#define ASTG_H (2*KVH)        // 9216 halves per stage

// Scratch (halves)
__device__ __half g_q[(size_t)MROWS * D_MODEL];
__device__ __half g_k[(size_t)MROWS * D_MODEL];
__device__ __half g_v[(size_t)MROWS * D_MODEL];
__device__ __half g_ctx[(size_t)MROWS * D_MODEL];
__device__ __half g_hx[(size_t)MROWS * D_MODEL];
__device__ __half g_hw[4 * (size_t)D_MODEL * D_MODEL];

// ---------------- PTX helpers ----------------
__device__ __forceinline__ uint32_t smem_u32(const void* p){
  uint32_t a;
  asm("{ .reg .u64 t; cvta.to.shared.u64 t, %1; cvt.u32.u64 %0, t; }" : "=r"(a) : "l"(p));
  return a;
}
__device__ __forceinline__ void cp_async16(uint32_t s, const void* g){
  asm volatile("cp.async.cg.shared.global [%0], [%1], 16;" :: "r"(s), "l"(g) : "memory");
}
__device__ __forceinline__ void cp_commit(){ asm volatile("cp.async.commit_group;" ::: "memory"); }
__device__ __forceinline__ void cp_wait0(){ asm volatile("cp.async.wait_group 0;" ::: "memory"); }
__device__ __forceinline__ void mma_f16(float* c, const uint32_t* a, const uint32_t* b){
  asm volatile(
    "mma.sync.aligned.m16n8k16.row.col.f32.f16.f16.f32 "
    "{%0,%1,%2,%3}, {%4,%5,%6,%7}, {%8,%9}, {%0,%1,%2,%3};"
    : "+f"(c[0]), "+f"(c[1]), "+f"(c[2]), "+f"(c[3])
    : "r"(a[0]), "r"(a[1]), "r"(a[2]), "r"(a[3]), "r"(b[0]), "r"(b[1]));
}
__device__ __forceinline__ void ldsm4(uint32_t* r, uint32_t addr){
  asm volatile("ldmatrix.sync.aligned.m8n8.x4.shared.b16 {%0,%1,%2,%3}, [%4];"
    : "=r"(r[0]), "=r"(r[1]), "=r"(r[2]), "=r"(r[3]) : "r"(addr));
}
__device__ __forceinline__ void ldsm4t(uint32_t* r, uint32_t addr){
  asm volatile("ldmatrix.sync.aligned.m8n8.x4.trans.shared.b16 {%0,%1,%2,%3}, [%4];"
    : "=r"(r[0]), "=r"(r[1]), "=r"(r[2]), "=r"(r[3]) : "r"(addr));
}
__device__ __forceinline__ uint32_t h2u(__half2 h){ return *(uint32_t*)&h; }

// ---------------------------------------------------------------------------
// Prep: convert X and the 4 weight matrices to fp16.
// ---------------------------------------------------------------------------
__global__ __launch_bounds__(256) void half_prep(
    const float4* __restrict__ X,
    const float4* __restrict__ Wq, const float4* __restrict__ Wk,
    const float4* __restrict__ Wv, const float4* __restrict__ Wo,
    __half2* __restrict__ hx, __half2* __restrict__ hw)
{
  const int XN = MROWS * D_MODEL / 4;
  const int WN = D_MODEL * D_MODEL / 4;
  const int total = XN + 4*WN;
  for (int i = blockIdx.x * 256 + threadIdx.x; i < total; i += gridDim.x * 256){
    const float4* src; __half2* dst; int j;
    if (i < XN){ src = X; dst = hx; j = i; }
    else {
      int w = (i - XN) / WN;
      j = (i - XN) - w*WN;
      src = (w == 0) ? Wq : (w == 1) ? Wk : (w == 2) ? Wv : Wo;
      dst = hw + (size_t)w * WN * 2;
    }
    float4 v = src[j];
    dst[2*j]   = __floats2half2_rn(v.x, v.y);
    dst[2*j+1] = __floats2half2_rn(v.z, v.w);
  }
}

// ---------------------------------------------------------------------------
// fp16 mma GEMM: C[4096,1024] = A @ W^T. mode 0: f32 out + bias.
// mode 1: half out; blockIdx.z==0 scaled by 1/64 (pre-scales q for attention).
// ---------------------------------------------------------------------------
static __device__ __forceinline__ void load_stage_g(
    uint32_t sA, uint32_t sW, const __half* A, const __half* W,
    int m0, int n0, int k0, int tid)
{
#pragma unroll
  for (int u = 0; u < 4; u++){
    int q = tid + u*256;          // 0..1023 chunks (8 halves = 16B)
    int r = q >> 3, c = q & 7;
    uint32_t so = (uint32_t)(r*GP + c*8) * 2u;
    cp_async16(sA + so, A + (size_t)(m0 + r)*D_MODEL + k0 + c*8);
    cp_async16(sW + so, W + (size_t)(n0 + r)*D_MODEL + k0 + c*8);
  }
}

__global__ __launch_bounds__(256) void gemm_h(
    const __half* __restrict__ A,
    const __half* __restrict__ Wa, const __half* __restrict__ Wb, const __half* __restrict__ Wc,
    void* __restrict__ Ca, void* __restrict__ Cb, void* __restrict__ Cc,
    const float* __restrict__ bias, int mode)
{
  const __half* W = (blockIdx.z == 0) ? Wa : (blockIdx.z == 1) ? Wb : Wc;
  void*         C = (blockIdx.z == 0) ? Ca : (blockIdx.z == 1) ? Cb : Cc;

  extern __shared__ __half smh[];
  const uint32_t sAu = smem_u32(smh);
  const uint32_t sWu = sAu + 2*STG_H*2;

  const int tid  = threadIdx.x;
  const int wid  = tid >> 5;
  const int lane = tid & 31;
  const int g    = lane >> 2;
  const int t4   = lane & 3;
  const int wm   = wid >> 2;
  const int wn   = wid & 3;
  const int m0   = blockIdx.y * 128;
  const int n0   = blockIdx.x * 128;

  // ldmatrix lane offsets (bytes)
  uint32_t a_off[4], b_off[2];
  {
    const int ra = (lane & 7) + ((lane >> 3) & 1) * 8;   // A row within 16
    const int ka = ((lane >> 4) & 1) * 8;                // A k-half offset (halves)
    const int rb = (lane & 7) + ((lane >> 4) & 1) * 8;   // B row within 16
    const int kb = ((lane >> 3) & 1) * 8;
#pragma unroll
    for (int mt = 0; mt < 4; mt++)
      a_off[mt] = (uint32_t)(((wm*64 + mt*16 + ra)*GP + ka) * 2);
#pragma unroll
    for (int np = 0; np < 2; np++)
      b_off[np] = (uint32_t)(((wn*32 + np*16 + rb)*GP + kb) * 2);
  }

  float c[4][4][4];
#pragma unroll
  for (int i = 0; i < 4; i++)
#pragma unroll
    for (int j = 0; j < 4; j++)
#pragma unroll
      for (int r = 0; r < 4; r++) c[i][j][r] = 0.0f;

  load_stage_g(sAu, sWu, A, W, m0, n0, 0, tid);
  cp_commit();

  for (int it = 0; it < GNIT; it++){
    const int s = it & 1;
    cp_wait0();
    __syncthreads();
    if (it + 1 < GNIT){
      const int sn = s ^ 1;
      load_stage_g(sAu + sn*STG_H*2, sWu + sn*STG_H*2, A, W, m0, n0, (it+1)*64, tid);
      cp_commit();
    }
    const uint32_t aBase = sAu + (uint32_t)s*STG_H*2u;
    const uint32_t bBase = sWu + (uint32_t)s*STG_H*2u;
#pragma unroll
    for (int ks = 0; ks < 4; ks++){
      const uint32_t kbyte = (uint32_t)(ks*32);
      uint32_t af[4][4], bf[2][4];
#pragma unroll
      for (int mt = 0; mt < 4; mt++) ldsm4(af[mt], aBase + a_off[mt] + kbyte);
#pragma unroll
      for (int np = 0; np < 2; np++) ldsm4(bf[np], bBase + b_off[np] + kbyte);
#pragma unroll
      for (int mt = 0; mt < 4; mt++)
#pragma unroll
        for (int nt = 0; nt < 4; nt++)
          mma_f16(c[mt][nt], af[mt], &bf[nt >> 1][(nt & 1)*2]);
    }
    __syncthreads();
  }

  if (mode == 1){
    const float s = (blockIdx.z == 0) ? 0.015625f : 1.0f;
    __half* Ch = (__half*)C;
#pragma unroll
    for (int mt = 0; mt < 4; mt++){
      const int r0 = m0 + wm*64 + mt*16 + g;
#pragma unroll
      for (int nt = 0; nt < 4; nt++){
        const int col = n0 + wn*32 + nt*8 + t4*2;
        *(__half2*)(Ch + (size_t)r0*D_MODEL + col)     = __floats2half2_rn(c[mt][nt][0]*s, c[mt][nt][1]*s);
        *(__half2*)(Ch + (size_t)(r0+8)*D_MODEL + col) = __floats2half2_rn(c[mt][nt][2]*s, c[mt][nt][3]*s);
      }
    }
  } else {
    float* Cf = (float*)C;
#pragma unroll
    for (int mt = 0; mt < 4; mt++){
      const int r0 = m0 + wm*64 + mt*16 + g;
#pragma unroll
      for (int nt = 0; nt < 4; nt++){
        const int col = n0 + wn*32 + nt*8 + t4*2;
        float b0 = bias ? bias[col] : 0.0f, b1 = bias ? bias[col+1] : 0.0f;
        *(float2*)&Cf[(size_t)r0*D_MODEL + col]     = make_float2(c[mt][nt][0]+b0, c[mt][nt][1]+b1);
        *(float2*)&Cf[(size_t)(r0+8)*D_MODEL + col] = make_float2(c[mt][nt][2]+b0, c[mt][nt][3]+b1);
      }
    }
  }
}

// ---------------------------------------------------------------------------
// fp16 mma flash attention. 256 thr / 8 warps; q-tile 128 (warp w: rows w*16+),
// k-tile 64 keys. Q pre-scaled by 1/64 in the QKV gemm.
// ---------------------------------------------------------------------------
static __device__ __forceinline__ void load_kv(
    uint32_t sb, int stage, const __half* Kt, const __half* Vt, int tid)
{
  const uint32_t base = sb + (uint32_t)stage * ASTG_H * 2u;
#pragma unroll
  for (int u = 0; u < 2; u++){
    int idx = tid + u*256;        // 0..511 chunks per operand
    int r = idx >> 3, c = idx & 7;
    uint32_t so = (uint32_t)(r*AP + c*8) * 2u;
    cp_async16(base + so, Kt + (size_t)r*HDIM + c*8);
    cp_async16(base + KVH*2u + so, Vt + (size_t)r*HDIM + c*8);
  }
}

__global__ __launch_bounds__(256) void attn_h(
    const __half* __restrict__ Qg, const __half* __restrict__ Kg,
    const __half* __restrict__ Vg, __half* __restrict__ ctx)
{
  extern __shared__ __half smh[];
  const uint32_t sb = smem_u32(smh);

  const int tid  = threadIdx.x;
  const int wid  = tid >> 5;
  const int lane = tid & 31;
  const int g    = lane >> 2;
  const int t4   = lane & 3;
  const int bh   = blockIdx.y;
  const int qt   = (int)gridDim.x - 1 - (int)blockIdx.x;   // heavy first
  const int qbase = qt * 128;

  const __half* Qh = Qg + (size_t)bh * SEQ * HDIM;
  const __half* Kh = Kg + (size_t)bh * SEQ * HDIM;
  const __half* Vh = Vg + (size_t)bh * SEQ * HDIM;

  // lane offsets
  uint32_t q_off, k_off[4], v_off;
  {
    const int ra = (lane & 7) + ((lane >> 3) & 1) * 8;     // A-row within 16
    const int ka = ((lane >> 4) & 1) * 8;
    q_off = (uint32_t)(((wid*16 + ra)*AP + ka) * 2);
    const int rb = (lane & 7) + ((lane >> 4) & 1) * 8;     // B-row within 16
    const int kb = ((lane >> 3) & 1) * 8;
#pragma unroll
    for (int np = 0; np < 4; np++)
      k_off[np] = (uint32_t)(((np*16 + rb)*AP + kb) * 2);
    const int kr = (lane & 7) + ((lane >> 3) & 1) * 8;     // V k-row within 16
    const int nc = ((lane >> 4) & 1) * 8;                  // V n-col offset
    v_off = (uint32_t)((kr*AP + nc) * 2);
  }

  // ---- stage Q (rows 0..127, pitch AP) into stage-0 area ----
#pragma unroll
  for (int u = 0; u < 4; u++){
    int idx = tid + u*256;        // 0..1023
    int r = idx >> 3, c = idx & 7;
    cp_async16(sb + (uint32_t)(r*AP + c*8)*2u, Qh + (size_t)(qbase + r)*HDIM + c*8);
  }
  cp_commit();
  cp_wait0();
  __syncthreads();

  uint32_t qa[4][4];
#pragma unroll
  for (int ks = 0; ks < 4; ks++) ldsm4(qa[ks], sb + q_off + (uint32_t)(ks*32));
  __syncthreads();

  float oc[8][4];
#pragma unroll
  for (int nb = 0; nb < 8; nb++)
#pragma unroll
    for (int r = 0; r < 4; r++) oc[nb][r] = 0.0f;
  float m0 = -1e30f, m1 = -1e30f, l0 = 0.0f, l1 = 0.0f;

  const int nkt = 2*qt + 2;
  load_kv(sb, 0, Kh, Vh, tid);
  cp_commit();

  const int grow0 = qbase + wid*16 + g;
  const int grow1 = grow0 + 8;

  for (int ki = 0; ki < nkt; ki++){
    const int s = ki & 1;
    cp_wait0();
    __syncthreads();
    if (ki + 1 < nkt){
      load_kv(sb, s ^ 1, Kh + (size_t)(ki+1)*64*HDIM, Vh + (size_t)(ki+1)*64*HDIM, tid);
      cp_commit();
    }
    const uint32_t kBase = sb + (uint32_t)s*ASTG_H*2u;
    const uint32_t vBase = kBase + KVH*2u;

    // ---- S = Q @ K^T ----
    float sc[8][4];
#pragma unroll
    for (int nb = 0; nb < 8; nb++)
#pragma unroll
      for (int r = 0; r < 4; r++) sc[nb][r] = 0.0f;
#pragma unroll
    for (int ks = 0; ks < 4; ks++){
      const uint32_t kbyte = (uint32_t)(ks*32);
#pragma unroll
      for (int np = 0; np < 4; np++){
        uint32_t kf[4];
        ldsm4(kf, kBase + k_off[np] + kbyte);
        mma_f16(sc[2*np],   qa[ks], &kf[0]);
        mma_f16(sc[2*np+1], qa[ks], &kf[2]);
      }
    }

    // ---- causal mask ----
    if (ki >= 2*qt){
      const int cb = ki*64 + 2*t4;
#pragma unroll
      for (int nb = 0; nb < 8; nb++){
        const int c0 = cb + 8*nb, c1 = c0 + 1;
        if (c0 > grow0) sc[nb][0] = -1e30f;
        if (c1 > grow0) sc[nb][1] = -1e30f;
        if (c0 > grow1) sc[nb][2] = -1e30f;
        if (c1 > grow1) sc[nb][3] = -1e30f;
      }
    }

    // ---- online softmax (rows quad-local) ----
    float mx0 = -1e30f, mx1 = -1e30f;
#pragma unroll
    for (int nb = 0; nb < 8; nb++){
      mx0 = fmaxf(mx0, fmaxf(sc[nb][0], sc[nb][1]));
      mx1 = fmaxf(mx1, fmaxf(sc[nb][2], sc[nb][3]));
    }
    mx0 = fmaxf(mx0, __shfl_xor_sync(0xffffffffu, mx0, 1));
    mx0 = fmaxf(mx0, __shfl_xor_sync(0xffffffffu, mx0, 2));
    mx1 = fmaxf(mx1, __shfl_xor_sync(0xffffffffu, mx1, 1));
    mx1 = fmaxf(mx1, __shfl_xor_sync(0xffffffffu, mx1, 2));
    const float mn0 = fmaxf(m0, mx0), mn1 = fmaxf(m1, mx1);
    const float al0 = __expf(m0 - mn0), al1 = __expf(m1 - mn1);
    m0 = mn0; m1 = mn1;

    uint32_t ph[8][2];            // [nb] {h2(p0,p1) rows g | h2(p2,p3) rows g+8}
    float sum0 = 0.0f, sum1 = 0.0f;
#pragma unroll
    for (int nb = 0; nb < 8; nb++){
      float p0 = __expf(sc[nb][0] - mn0);
      float p1 = __expf(sc[nb][1] - mn0);
      float p2 = __expf(sc[nb][2] - mn1);
      float p3 = __expf(sc[nb][3] - mn1);
      sum0 += p0 + p1; sum1 += p2 + p3;
      ph[nb][0] = h2u(__floats2half2_rn(p0, p1));
      ph[nb][1] = h2u(__floats2half2_rn(p2, p3));
    }
    sum0 += __shfl_xor_sync(0xffffffffu, sum0, 1);
    sum0 += __shfl_xor_sync(0xffffffffu, sum0, 2);
    sum1 += __shfl_xor_sync(0xffffffffu, sum1, 1);
    sum1 += __shfl_xor_sync(0xffffffffu, sum1, 2);
    l0 = l0*al0 + sum0; l1 = l1*al1 + sum1;
#pragma unroll
    for (int nb = 0; nb < 8; nb++){
      oc[nb][0] *= al0; oc[nb][1] *= al0;
      oc[nb][2] *= al1; oc[nb][3] *= al1;
    }

    // ---- O += P @ V (A-frags come straight from P fragments; V via ldsm.trans)
#pragma unroll
    for (int ks = 0; ks < 4; ks++){
      uint32_t a[4];
      a[0] = ph[2*ks][0];   a[1] = ph[2*ks][1];
      a[2] = ph[2*ks+1][0]; a[3] = ph[2*ks+1][1];
      const uint32_t vrow = (uint32_t)(ks*16*AP*2);
#pragma unroll
      for (int nb16 = 0; nb16 < 4; nb16++){
        uint32_t vf[4];
        ldsm4t(vf, vBase + v_off + vrow + (uint32_t)(nb16*32));
        mma_f16(oc[2*nb16],   a, &vf[0]);
        mma_f16(oc[2*nb16+1], a, &vf[2]);
      }
    }
  }

  // ---- epilogue: normalize, write ctx half ----
  const int b = bh >> 4, h = bh & 15;
  const float inv0 = 1.0f / l0, inv1 = 1.0f / l1;
  __half* base0 = ctx + ((size_t)(b*SEQ + grow0)) * D_MODEL + h*HDIM;
#pragma unroll
  for (int nb = 0; nb < 8; nb++){
    const int col = 8*nb + 2*t4;
    *(__half2*)(base0 + col) = __floats2half2_rn(oc[nb][0]*inv0, oc[nb][1]*inv0);
    *(__half2*)(base0 + 8*(size_t)D_MODEL + col) = __floats2half2_rn(oc[nb][2]*inv1, oc[nb][3]*inv1);
  }
}

// ---------------------------------------------------------------------------
extern "C" void kernel_launch(void* const* d_in, const int* in_sizes, int n_in,
                              void* d_out, int out_size)
{
    const float* X  = (const float*)d_in[0];
    const float* Wq = (const float*)d_in[1];
    const float* Wk = (const float*)d_in[2];
    const float* Wv = (const float*)d_in[3];
    const float* Wo = (const float*)d_in[4];
    const float* bo = (const float*)d_in[5];
    float* out = (float*)d_out;

    __half *pq, *pk, *pv, *pctx, *phx, *phw;
    cudaGetSymbolAddress((void**)&pq,  g_q);
    cudaGetSymbolAddress((void**)&pk,  g_k);
    cudaGetSymbolAddress((void**)&pv,  g_v);
    cudaGetSymbolAddress((void**)&pctx, g_ctx);
    cudaGetSymbolAddress((void**)&phx, g_hx);
    cudaGetSymbolAddress((void**)&phw, g_hw);

    const size_t WSZ = (size_t)D_MODEL * D_MODEL;
    const __half* hWq = phw;
    const __half* hWk = phw + WSZ;
    const __half* hWv = phw + 2*WSZ;
    const __half* hWo = phw + 3*WSZ;

    half_prep<<<592, 256>>>((const float4*)X, (const float4*)Wq, (const float4*)Wk,
                            (const float4*)Wv, (const float4*)Wo,
                            (__half2*)phx, (__half2*)phw);

    const int gsmem = 4 * STG_H * 2;   // 73728 B
    cudaFuncSetAttribute(gemm_h, cudaFuncAttributeMaxDynamicSharedMemorySize, gsmem);

    // QKV projections (half out; z==0 (q) pre-scaled by 1/64)
    gemm_h<<<dim3(8, 32, 3), 256, gsmem>>>(phx, hWq, hWk, hWv, pq, pk, pv, nullptr, 1);

    const int asmem = 2 * ASTG_H * 2;  // 36864 B
    cudaFuncSetAttribute(attn_h, cudaFuncAttributeMaxDynamicSharedMemorySize, asmem);
    attn_h<<<dim3(SEQ/128, BATCH*HEADS), 256, asmem>>>(pq, pk, pv, pctx);

    // Output projection + bias (f32 out)
    gemm_h<<<dim3(8, 32, 1), 256, gsmem>>>(pctx, hWo, hWo, hWo, out, out, out, bo, 0);
}